// round 5
// baseline (speedup 1.0000x reference)
#include <cuda_runtime.h>
#include <cstdint>

// ---------------------------------------------------------------------------
// Problem: 4 coupled LSTMs, B=1, T=8000, F=U=512.
//   pass0: real x Wr/Rr   pass1: real x Wi/Ri
//   pass2: imag x Wr/Rr   pass3: imag x Wi/Ri
//   real_out = h0 - h3 ; imag_out = h2 + h1 ; out_states = final (h,c) per pass
// ---------------------------------------------------------------------------

#define T_STEPS 8000
#define UDIM    512
#define GDIM    2048   // 4*U

// Scratch (allocation-free rule: __device__ globals)
__device__ float    g_xz[4ULL * T_STEPS * GDIM];      // 262 MB: input projections
__device__ float    g_H [4ULL * (T_STEPS + 1) * UDIM]; // 65.5 MB: h history (slot 0 = h_init)
__device__ unsigned g_done[128];                      // per-CTA barrier flags (monotonic)

// ---------------------------------------------------------------------------
// helpers
// ---------------------------------------------------------------------------
__device__ __forceinline__ float2 ffma2(float2 a, float2 b, float2 c) {
    unsigned long long ua = *reinterpret_cast<unsigned long long*>(&a);
    unsigned long long ub = *reinterpret_cast<unsigned long long*>(&b);
    unsigned long long uc = *reinterpret_cast<unsigned long long*>(&c);
    unsigned long long ud;
    asm("fma.rn.f32x2 %0, %1, %2, %3;" : "=l"(ud) : "l"(ua), "l"(ub), "l"(uc));
    return *reinterpret_cast<float2*>(&ud);
}

__device__ __forceinline__ unsigned ld_acq(const unsigned* p) {
    unsigned v;
    asm volatile("ld.acquire.gpu.global.u32 %0, [%1];" : "=r"(v) : "l"(p) : "memory");
    return v;
}
__device__ __forceinline__ void st_rel(unsigned* p, unsigned v) {
    asm volatile("st.release.gpu.global.u32 [%0], %1;" :: "l"(p), "r"(v) : "memory");
}

__device__ __forceinline__ float sigf(float x) {
    // NaN-safe for large |x|: expf(-x)->inf gives 0, ->0 gives 1
    return 1.0f / (1.0f + __expf(-x));
}
__device__ __forceinline__ float tanh_fast(float x) {
    // 1 - 2/(1+e^{2x}) : -> -1 for x->-inf, +1 for x->+inf, no inf/inf
    return 1.0f - 2.0f / (1.0f + __expf(2.0f * x));
}

// ---------------------------------------------------------------------------
// init: copy initial h into g_H[p][0][*]
// in_states flat layout [4][512][2] : (..,0)=h, (..,1)=c
// ---------------------------------------------------------------------------
__global__ void init_kernel(const float* __restrict__ states) {
    int idx = blockIdx.x * blockDim.x + threadIdx.x;
    if (idx < 4 * UDIM) {
        int p = idx >> 9, u = idx & 511;
        g_H[(size_t)p * (T_STEPS + 1) * UDIM + u] = states[p * (UDIM * 2) + u * 2 + 0];
    }
}

// ---------------------------------------------------------------------------
// GEMM: xz[p] = X[p] @ W[p] + bias[p], X [8000x512] row-major, W [512x2048]
// 128x128 tile, BK=8, 256 threads, 8x8 micro-tile with f32x2 packed FMA.
// ---------------------------------------------------------------------------
#define BM 128
#define BN 128
#define BK 8

__global__ __launch_bounds__(256, 2) void gemm_kernel(
    const float* __restrict__ Xr, const float* __restrict__ Xi,
    const float* __restrict__ Wr, const float* __restrict__ Wi,
    const float* __restrict__ br, const float* __restrict__ bi)
{
    const int p = blockIdx.z;
    const float* X    = (p >= 2) ? Xi : Xr;
    const float* W    = (p & 1) ? Wi : Wr;
    const float* bias = (p & 1) ? bi : br;
    float* C = g_xz + (size_t)p * T_STEPS * GDIM;

    const int bm = blockIdx.y * BM;
    const int bn = blockIdx.x * BN;

    __shared__ float As[BK][BM];
    __shared__ float Bs[BK][BN];

    const int tid = threadIdx.x;
    const int tx = tid & 15;   // 0..15  -> col group
    const int ty = tid >> 4;   // 0..15  -> row group

    // global load mapping
    const int arow = tid >> 1;         // 0..127
    const int acol = (tid & 1) * 4;    // 0 or 4
    const int brow = tid >> 6;         // 0..3 (need 8 rows -> two loads)
    const int bcol = (tid & 63) * 4;   // hmm 64*4 = 256 > 128 -> fix below

    float2 acc[8][4];
#pragma unroll
    for (int m = 0; m < 8; m++)
#pragma unroll
        for (int n = 0; n < 4; n++) acc[m][n] = make_float2(0.f, 0.f);

    // B load mapping: 8 rows x 128 cols = 1024 floats / 256 thr = 1 float4 each
    const int b_r = tid >> 5;        // 0..7
    const int b_c = (tid & 31) * 4;  // 0..124

    for (int k0 = 0; k0 < 512; k0 += BK) {
        // A tile: 128 rows x 8 k : 1 float4 per thread
        float4 av = make_float4(0.f, 0.f, 0.f, 0.f);
        int m_g = bm + arow;
        if (m_g < T_STEPS)
            av = *reinterpret_cast<const float4*>(X + (size_t)m_g * 512 + k0 + acol);
        As[acol + 0][arow] = av.x;
        As[acol + 1][arow] = av.y;
        As[acol + 2][arow] = av.z;
        As[acol + 3][arow] = av.w;

        float4 bv = *reinterpret_cast<const float4*>(W + (size_t)(k0 + b_r) * GDIM + bn + b_c);
        *reinterpret_cast<float4*>(&Bs[b_r][b_c]) = bv;

        __syncthreads();

#pragma unroll
        for (int k = 0; k < BK; k++) {
            float4 a0 = *reinterpret_cast<float4*>(&As[k][ty * 8]);
            float4 a1 = *reinterpret_cast<float4*>(&As[k][ty * 8 + 4]);
            float4 b0 = *reinterpret_cast<float4*>(&Bs[k][tx * 8]);
            float4 b1 = *reinterpret_cast<float4*>(&Bs[k][tx * 8 + 4]);
            float  a[8] = {a0.x, a0.y, a0.z, a0.w, a1.x, a1.y, a1.z, a1.w};
            float2 bp[4] = {make_float2(b0.x, b0.y), make_float2(b0.z, b0.w),
                            make_float2(b1.x, b1.y), make_float2(b1.z, b1.w)};
#pragma unroll
            for (int m = 0; m < 8; m++) {
                float2 am = make_float2(a[m], a[m]);
#pragma unroll
                for (int n = 0; n < 4; n++)
                    acc[m][n] = ffma2(am, bp[n], acc[m][n]);
            }
        }
        __syncthreads();
    }

    // store with bias
#pragma unroll
    for (int m = 0; m < 8; m++) {
        int row = bm + ty * 8 + m;
        if (row < T_STEPS) {
#pragma unroll
            for (int n = 0; n < 4; n++) {
                int col = bn + tx * 8 + n * 2;
                float2 r = acc[m][n];
                r.x += bias[col];
                r.y += bias[col + 1];
                *reinterpret_cast<float2*>(C + (size_t)row * GDIM + col) = r;
            }
        }
    }
}

// ---------------------------------------------------------------------------
// Persistent recurrent kernel.
// 128 CTAs x 256 threads. CTAs 0..63: weight set Rr, passes {0,2}.
//                         CTAs 64..127: weight set Ri, passes {1,3}.
// Each CTA owns 8 units; warp w = unit (cta&63)*8+w. Weights live in regs
// as f32x2 pairs (rows r and r+256). Per step: barrier within 64-CTA group,
// stage h to smem (pre-paired), 64 f32x2 FMA per lane, butterfly reduce,
// warp0 lanes 0..15 run gate nonlinearities and carry c.
// ---------------------------------------------------------------------------
__global__ __launch_bounds__(256, 1) void rnn_kernel(
    const float* __restrict__ Rr, const float* __restrict__ Ri,
    const float* __restrict__ states, float* __restrict__ out)
{
    const int cta  = blockIdx.x;
    const int tid  = threadIdx.x;
    const int w    = tid >> 5;
    const int lane = tid & 31;
    const int grp  = cta >> 6;   // 0 = real weight set, 1 = imag weight set
    const int cu   = cta & 63;
    const int unit = cu * 8 + w;

    const float* R = grp ? Ri : Rr;

    __shared__ float2   shp[2][8][32]; // [q][j][lane] = (h[32j+lane], h[32j+256+lane])
    __shared__ float    zsm[8][8];     // [warp][g*2+q]
    __shared__ unsigned sbase;

    // ---- load this warp's weight columns into registers (one-time) ----
    float2 wv[4][8];
#pragma unroll
    for (int g = 0; g < 4; g++) {
        const int col = g * UDIM + unit;
#pragma unroll
        for (int j = 0; j < 8; j++) {
            wv[g][j].x = R[(size_t)(32 * j + lane) * GDIM + col];
            wv[g][j].y = R[(size_t)(32 * j + 256 + lane) * GDIM + col];
        }
    }

    // ---- warp0 per-lane recurrent state ----
    const int q      = lane & 1;
    const int uj     = lane >> 1;
    const int myp    = (grp == 0) ? (q ? 2 : 0) : (q ? 3 : 1);
    const int myunit = cu * 8 + uj;
    float c = 0.f, hlast = 0.f;
    if (w == 0 && lane < 16)
        c = states[myp * (UDIM * 2) + myunit * 2 + 1];

    const int pA = grp ? 1 : 0;
    const int pB = grp ? 3 : 2;

    // barrier base: read own slot (stable — only our warp0 ever writes it)
    if (tid == 0) sbase = ld_acq(&g_done[cta]);
    __syncthreads();
    const unsigned base = sbase;

    const int s_ln = tid & 31;
    const int s_j  = (tid >> 5) & 7;

    for (int t = 0; t < T_STEPS; t++) {
        // prefetch xz for this step (independent of the barrier)
        float xzi, xzf, xzg, xzo;
        if (w == 0 && lane < 16) {
            const float* xp = g_xz + ((size_t)myp * T_STEPS + t) * GDIM + myunit;
            xzi = xp[0];
            xzf = xp[UDIM];
            xzg = xp[2 * UDIM];
            xzo = xp[3 * UDIM];
        }

        // wait for all CTAs in this group to have published h(t)
        if (t > 0 && tid < 64) {
            const unsigned tgt = base + (unsigned)t;
            const unsigned* fp = &g_done[grp * 64 + tid];
            while (ld_acq(fp) < tgt) { }
        }
        __syncthreads();

        // stage h(t) for both passes into smem, pre-paired for f32x2
        {
            const float* hA = g_H + ((size_t)pA * (T_STEPS + 1) + t) * UDIM;
            const float* hB = g_H + ((size_t)pB * (T_STEPS + 1) + t) * UDIM;
            shp[0][s_j][s_ln] = make_float2(hA[32 * s_j + s_ln], hA[32 * s_j + 256 + s_ln]);
            shp[1][s_j][s_ln] = make_float2(hB[32 * s_j + s_ln], hB[32 * s_j + 256 + s_ln]);
        }
        __syncthreads();

        // z partials: 4 gates x 2 passes, packed over row pairs
        float2 acc[4][2];
#pragma unroll
        for (int g = 0; g < 4; g++) {
            acc[g][0] = make_float2(0.f, 0.f);
            acc[g][1] = make_float2(0.f, 0.f);
        }
#pragma unroll
        for (int j = 0; j < 8; j++) {
            float2 h0 = shp[0][j][lane];
            float2 h1 = shp[1][j][lane];
#pragma unroll
            for (int g = 0; g < 4; g++) {
                acc[g][0] = ffma2(wv[g][j], h0, acc[g][0]);
                acc[g][1] = ffma2(wv[g][j], h1, acc[g][1]);
            }
        }
        float s[8];
#pragma unroll
        for (int g = 0; g < 4; g++) {
            s[g * 2 + 0] = acc[g][0].x + acc[g][0].y;
            s[g * 2 + 1] = acc[g][1].x + acc[g][1].y;
        }
#pragma unroll
        for (int off = 16; off; off >>= 1) {
#pragma unroll
            for (int k = 0; k < 8; k++)
                s[k] += __shfl_xor_sync(0xffffffffu, s[k], off);
        }
        if (lane == 0) {
#pragma unroll
            for (int k = 0; k < 8; k++) zsm[w][k] = s[k];
        }
        __syncthreads();

        // warp0: gates + state update for all 16 (unit,pass) pairs of this CTA
        if (w == 0) {
            if (lane < 16) {
                float zi = zsm[uj][0 + q] + xzi;
                float zf = zsm[uj][2 + q] + xzf;
                float zg = zsm[uj][4 + q] + xzg;
                float zo = zsm[uj][6 + q] + xzo;
                float si = sigf(zi);
                float sf = sigf(zf);
                float tg = tanh_fast(zg);
                float so = sigf(zo);
                c = fmaf(sf, c, si * tg);
                float h = so * tanh_fast(c);
                hlast = h;
                g_H[((size_t)myp * (T_STEPS + 1) + (t + 1)) * UDIM + myunit] = h;
            }
            __syncwarp();
            if (lane == 0) {
                __threadfence();
                st_rel(&g_done[cta], base + (unsigned)t + 1u);
            }
        }
    }

    // final states -> out_states region: out[8192000 + p*1024 + u*2 + {0:h,1:c}]
    if (w == 0 && lane < 16) {
        float* os = out + (size_t)2 * T_STEPS * UDIM;
        os[myp * (UDIM * 2) + myunit * 2 + 0] = hlast;
        os[myp * (UDIM * 2) + myunit * 2 + 1] = c;
    }
}

// ---------------------------------------------------------------------------
// combine: real = h0 - h3, imag = h2 + h1  (element i over T*U, float4)
// ---------------------------------------------------------------------------
__global__ void combine_kernel(float* __restrict__ out)
{
    const int i = blockIdx.x * blockDim.x + threadIdx.x; // float4 index
    const int n4 = (T_STEPS * UDIM) / 4;                 // 1,024,000
    if (i < n4) {
        const float4* H0 = reinterpret_cast<const float4*>(g_H + 0ULL * (T_STEPS + 1) * UDIM + UDIM);
        const float4* H1 = reinterpret_cast<const float4*>(g_H + 1ULL * (T_STEPS + 1) * UDIM + UDIM);
        const float4* H2 = reinterpret_cast<const float4*>(g_H + 2ULL * (T_STEPS + 1) * UDIM + UDIM);
        const float4* H3 = reinterpret_cast<const float4*>(g_H + 3ULL * (T_STEPS + 1) * UDIM + UDIM);
        float4 a = H0[i], b = H1[i], cc = H2[i], d = H3[i];
        float4 re, im;
        re.x = a.x - d.x; re.y = a.y - d.y; re.z = a.z - d.z; re.w = a.w - d.w;
        im.x = cc.x + b.x; im.y = cc.y + b.y; im.z = cc.z + b.z; im.w = cc.w + b.w;
        float4* o_re = reinterpret_cast<float4*>(out);
        float4* o_im = reinterpret_cast<float4*>(out + (size_t)T_STEPS * UDIM);
        o_re[i] = re;
        o_im[i] = im;
    }
}

// ---------------------------------------------------------------------------
extern "C" void kernel_launch(void* const* d_in, const int* in_sizes, int n_in,
                              void* d_out, int out_size)
{
    const float* in_real = (const float*)d_in[0];
    const float* in_imag = (const float*)d_in[1];
    const float* states  = (const float*)d_in[2];
    const float* Wr      = (const float*)d_in[3];
    const float* Rr      = (const float*)d_in[4];
    const float* br      = (const float*)d_in[5];
    const float* Wi      = (const float*)d_in[6];
    const float* Ri      = (const float*)d_in[7];
    const float* bi      = (const float*)d_in[8];
    float* out = (float*)d_out;

    init_kernel<<<2, 1024>>>(states);

    dim3 gg(GDIM / BN, (T_STEPS + BM - 1) / BM, 4); // (16, 63, 4)
    gemm_kernel<<<gg, 256>>>(in_real, in_imag, Wr, Wi, br, bi);

    rnn_kernel<<<128, 256>>>(Rr, Ri, states, out);

    combine_kernel<<<(T_STEPS * UDIM / 4 + 255) / 256, 256>>>(out);
}

// round 7
// speedup vs baseline: 1.8435x; 1.8435x over previous
#include <cuda_runtime.h>
#include <cstdint>

// ---------------------------------------------------------------------------
// Problem: 4 coupled LSTMs, B=1, T=8000, F=U=512.
//   pass0: real x Wr/Rr   pass1: real x Wi/Ri
//   pass2: imag x Wr/Rr   pass3: imag x Wi/Ri
//   real_out = h0 - h3 ; imag_out = h2 + h1 ; out_states = final (h,c) per pass
// ---------------------------------------------------------------------------

#define T_STEPS 8000
#define UDIM    512
#define GDIM    2048   // 4*U

// Scratch (allocation-free rule: __device__ globals)
__device__ float    g_xz[4ULL * T_STEPS * GDIM];      // 262 MB: input projections
__device__ float    g_H [4ULL * (T_STEPS + 1) * UDIM]; // 65.5 MB: h history (slot 0 = h_init)
__device__ unsigned g_done[128];                      // per-CTA barrier flags (monotonic)

// ---------------------------------------------------------------------------
// helpers
// ---------------------------------------------------------------------------
__device__ __forceinline__ float2 ffma2(float2 a, float2 b, float2 c) {
    unsigned long long ua = *reinterpret_cast<unsigned long long*>(&a);
    unsigned long long ub = *reinterpret_cast<unsigned long long*>(&b);
    unsigned long long uc = *reinterpret_cast<unsigned long long*>(&c);
    unsigned long long ud;
    asm("fma.rn.f32x2 %0, %1, %2, %3;" : "=l"(ud) : "l"(ua), "l"(ub), "l"(uc));
    return *reinterpret_cast<float2*>(&ud);
}

__device__ __forceinline__ unsigned ld_acq(const unsigned* p) {
    unsigned v;
    asm volatile("ld.acquire.gpu.global.u32 %0, [%1];" : "=r"(v) : "l"(p) : "memory");
    return v;
}
__device__ __forceinline__ void st_rel(unsigned* p, unsigned v) {
    asm volatile("st.release.gpu.global.u32 [%0], %1;" :: "l"(p), "r"(v) : "memory");
}

__device__ __forceinline__ float sigf(float x) {
    // NaN-safe for large |x|: expf(-x)->inf gives 0, ->0 gives 1
    return 1.0f / (1.0f + __expf(-x));
}
__device__ __forceinline__ float tanh_fast(float x) {
    // 1 - 2/(1+e^{2x}) : -> -1 for x->-inf, +1 for x->+inf, no inf/inf
    return 1.0f - 2.0f / (1.0f + __expf(2.0f * x));
}

// ---------------------------------------------------------------------------
// init: copy initial h into g_H[p][0][*]
// in_states flat layout [4][512][2] : (..,0)=h, (..,1)=c
// ---------------------------------------------------------------------------
__global__ void init_kernel(const float* __restrict__ states) {
    int idx = blockIdx.x * blockDim.x + threadIdx.x;
    if (idx < 4 * UDIM) {
        int p = idx >> 9, u = idx & 511;
        g_H[(size_t)p * (T_STEPS + 1) * UDIM + u] = states[p * (UDIM * 2) + u * 2 + 0];
    }
}

// ---------------------------------------------------------------------------
// GEMM: xz[p] = X[p] @ W[p] + bias[p], X [8000x512] row-major, W [512x2048]
// 128x128 tile, BK=8, 256 threads, 8x8 micro-tile with f32x2 packed FMA.
// ---------------------------------------------------------------------------
#define BM 128
#define BN 128
#define BK 8

__global__ __launch_bounds__(256, 2) void gemm_kernel(
    const float* __restrict__ Xr, const float* __restrict__ Xi,
    const float* __restrict__ Wr, const float* __restrict__ Wi,
    const float* __restrict__ br, const float* __restrict__ bi)
{
    const int p = blockIdx.z;
    const float* X    = (p >= 2) ? Xi : Xr;
    const float* W    = (p & 1) ? Wi : Wr;
    const float* bias = (p & 1) ? bi : br;
    float* C = g_xz + (size_t)p * T_STEPS * GDIM;

    const int bm = blockIdx.y * BM;
    const int bn = blockIdx.x * BN;

    __shared__ float As[BK][BM];
    __shared__ float Bs[BK][BN];

    const int tid = threadIdx.x;
    const int tx = tid & 15;   // 0..15  -> col group
    const int ty = tid >> 4;   // 0..15  -> row group

    // global load mapping
    const int arow = tid >> 1;         // 0..127
    const int acol = (tid & 1) * 4;    // 0 or 4
    const int brow = tid >> 6;         // 0..3 (need 8 rows -> two loads)
    const int bcol = (tid & 63) * 4;   // hmm 64*4 = 256 > 128 -> fix below

    float2 acc[8][4];
#pragma unroll
    for (int m = 0; m < 8; m++)
#pragma unroll
        for (int n = 0; n < 4; n++) acc[m][n] = make_float2(0.f, 0.f);

    // B load mapping: 8 rows x 128 cols = 1024 floats / 256 thr = 1 float4 each
    const int b_r = tid >> 5;        // 0..7
    const int b_c = (tid & 31) * 4;  // 0..124

    for (int k0 = 0; k0 < 512; k0 += BK) {
        // A tile: 128 rows x 8 k : 1 float4 per thread
        float4 av = make_float4(0.f, 0.f, 0.f, 0.f);
        int m_g = bm + arow;
        if (m_g < T_STEPS)
            av = *reinterpret_cast<const float4*>(X + (size_t)m_g * 512 + k0 + acol);
        As[acol + 0][arow] = av.x;
        As[acol + 1][arow] = av.y;
        As[acol + 2][arow] = av.z;
        As[acol + 3][arow] = av.w;

        float4 bv = *reinterpret_cast<const float4*>(W + (size_t)(k0 + b_r) * GDIM + bn + b_c);
        *reinterpret_cast<float4*>(&Bs[b_r][b_c]) = bv;

        __syncthreads();

#pragma unroll
        for (int k = 0; k < BK; k++) {
            float4 a0 = *reinterpret_cast<float4*>(&As[k][ty * 8]);
            float4 a1 = *reinterpret_cast<float4*>(&As[k][ty * 8 + 4]);
            float4 b0 = *reinterpret_cast<float4*>(&Bs[k][tx * 8]);
            float4 b1 = *reinterpret_cast<float4*>(&Bs[k][tx * 8 + 4]);
            float  a[8] = {a0.x, a0.y, a0.z, a0.w, a1.x, a1.y, a1.z, a1.w};
            float2 bp[4] = {make_float2(b0.x, b0.y), make_float2(b0.z, b0.w),
                            make_float2(b1.x, b1.y), make_float2(b1.z, b1.w)};
#pragma unroll
            for (int m = 0; m < 8; m++) {
                float2 am = make_float2(a[m], a[m]);
#pragma unroll
                for (int n = 0; n < 4; n++)
                    acc[m][n] = ffma2(am, bp[n], acc[m][n]);
            }
        }
        __syncthreads();
    }

    // store with bias
#pragma unroll
    for (int m = 0; m < 8; m++) {
        int row = bm + ty * 8 + m;
        if (row < T_STEPS) {
#pragma unroll
            for (int n = 0; n < 4; n++) {
                int col = bn + tx * 8 + n * 2;
                float2 r = acc[m][n];
                r.x += bias[col];
                r.y += bias[col + 1];
                *reinterpret_cast<float2*>(C + (size_t)row * GDIM + col) = r;
            }
        }
    }
}

// ---------------------------------------------------------------------------
// Persistent recurrent kernel.
// 128 CTAs x 256 threads. CTAs 0..63: weight set Rr, passes {0,2}.
//                         CTAs 64..127: weight set Ri, passes {1,3}.
// Each CTA owns 8 units; warp w = unit (cta&63)*8+w. Weights live in regs
// as f32x2 pairs (rows r and r+256). Per step: barrier within 64-CTA group,
// stage h to smem (pre-paired), 64 f32x2 FMA per lane, butterfly reduce,
// warp0 lanes 0..15 run gate nonlinearities and carry c.
// ---------------------------------------------------------------------------
__global__ __launch_bounds__(256, 1) void rnn_kernel(
    const float* __restrict__ Rr, const float* __restrict__ Ri,
    const float* __restrict__ states, float* __restrict__ out)
{
    const int cta  = blockIdx.x;
    const int tid  = threadIdx.x;
    const int w    = tid >> 5;
    const int lane = tid & 31;
    const int grp  = cta >> 6;   // 0 = real weight set, 1 = imag weight set
    const int cu   = cta & 63;
    const int unit = cu * 8 + w;

    const float* R = grp ? Ri : Rr;

    __shared__ float2   shp[2][8][32]; // [q][j][lane] = (h[32j+lane], h[32j+256+lane])
    __shared__ float    zsm[8][8];     // [warp][g*2+q]
    __shared__ unsigned sbase;

    // ---- load this warp's weight columns into registers (one-time) ----
    float2 wv[4][8];
#pragma unroll
    for (int g = 0; g < 4; g++) {
        const int col = g * UDIM + unit;
#pragma unroll
        for (int j = 0; j < 8; j++) {
            wv[g][j].x = R[(size_t)(32 * j + lane) * GDIM + col];
            wv[g][j].y = R[(size_t)(32 * j + 256 + lane) * GDIM + col];
        }
    }

    // ---- warp0 per-lane recurrent state ----
    const int q      = lane & 1;
    const int uj     = lane >> 1;
    const int myp    = (grp == 0) ? (q ? 2 : 0) : (q ? 3 : 1);
    const int myunit = cu * 8 + uj;
    float c = 0.f, hlast = 0.f;
    if (w == 0 && lane < 16)
        c = states[myp * (UDIM * 2) + myunit * 2 + 1];

    const int pA = grp ? 1 : 0;
    const int pB = grp ? 3 : 2;

    // barrier base: read own slot (stable — only our warp0 ever writes it)
    if (tid == 0) sbase = ld_acq(&g_done[cta]);
    __syncthreads();
    const unsigned base = sbase;

    const int s_ln = tid & 31;
    const int s_j  = (tid >> 5) & 7;

    for (int t = 0; t < T_STEPS; t++) {
        // prefetch xz for this step (independent of the barrier)
        float xzi, xzf, xzg, xzo;
        if (w == 0 && lane < 16) {
            const float* xp = g_xz + ((size_t)myp * T_STEPS + t) * GDIM + myunit;
            xzi = xp[0];
            xzf = xp[UDIM];
            xzg = xp[2 * UDIM];
            xzo = xp[3 * UDIM];
        }

        // wait for all CTAs in this group to have published h(t)
        if (t > 0 && tid < 64) {
            const unsigned tgt = base + (unsigned)t;
            const unsigned* fp = &g_done[grp * 64 + tid];
            while (ld_acq(fp) < tgt) { }
        }
        __syncthreads();

        // stage h(t) for both passes into smem, pre-paired for f32x2
        {
            const float* hA = g_H + ((size_t)pA * (T_STEPS + 1) + t) * UDIM;
            const float* hB = g_H + ((size_t)pB * (T_STEPS + 1) + t) * UDIM;
            shp[0][s_j][s_ln] = make_float2(hA[32 * s_j + s_ln], hA[32 * s_j + 256 + s_ln]);
            shp[1][s_j][s_ln] = make_float2(hB[32 * s_j + s_ln], hB[32 * s_j + 256 + s_ln]);
        }
        __syncthreads();

        // z partials: 4 gates x 2 passes, packed over row pairs
        float2 acc[4][2];
#pragma unroll
        for (int g = 0; g < 4; g++) {
            acc[g][0] = make_float2(0.f, 0.f);
            acc[g][1] = make_float2(0.f, 0.f);
        }
#pragma unroll
        for (int j = 0; j < 8; j++) {
            float2 h0 = shp[0][j][lane];
            float2 h1 = shp[1][j][lane];
#pragma unroll
            for (int g = 0; g < 4; g++) {
                acc[g][0] = ffma2(wv[g][j], h0, acc[g][0]);
                acc[g][1] = ffma2(wv[g][j], h1, acc[g][1]);
            }
        }
        float s[8];
#pragma unroll
        for (int g = 0; g < 4; g++) {
            s[g * 2 + 0] = acc[g][0].x + acc[g][0].y;
            s[g * 2 + 1] = acc[g][1].x + acc[g][1].y;
        }
#pragma unroll
        for (int off = 16; off; off >>= 1) {
#pragma unroll
            for (int k = 0; k < 8; k++)
                s[k] += __shfl_xor_sync(0xffffffffu, s[k], off);
        }
        if (lane == 0) {
#pragma unroll
            for (int k = 0; k < 8; k++) zsm[w][k] = s[k];
        }
        __syncthreads();

        // warp0: gates + state update for all 16 (unit,pass) pairs of this CTA
        if (w == 0) {
            if (lane < 16) {
                float zi = zsm[uj][0 + q] + xzi;
                float zf = zsm[uj][2 + q] + xzf;
                float zg = zsm[uj][4 + q] + xzg;
                float zo = zsm[uj][6 + q] + xzo;
                float si = sigf(zi);
                float sf = sigf(zf);
                float tg = tanh_fast(zg);
                float so = sigf(zo);
                c = fmaf(sf, c, si * tg);
                float h = so * tanh_fast(c);
                hlast = h;
                g_H[((size_t)myp * (T_STEPS + 1) + (t + 1)) * UDIM + myunit] = h;
            }
            __syncwarp();
            if (lane == 0) {
                __threadfence();
                st_rel(&g_done[cta], base + (unsigned)t + 1u);
            }
        }
    }

    // final states -> out_states region: out[8192000 + p*1024 + u*2 + {0:h,1:c}]
    if (w == 0 && lane < 16) {
        float* os = out + (size_t)2 * T_STEPS * UDIM;
        os[myp * (UDIM * 2) + myunit * 2 + 0] = hlast;
        os[myp * (UDIM * 2) + myunit * 2 + 1] = c;
    }
}

// ---------------------------------------------------------------------------
// combine: real = h0 - h3, imag = h2 + h1  (element i over T*U, float4)
// ---------------------------------------------------------------------------
__global__ void combine_kernel(float* __restrict__ out)
{
    const int i = blockIdx.x * blockDim.x + threadIdx.x; // float4 index
    const int n4 = (T_STEPS * UDIM) / 4;                 // 1,024,000
    if (i < n4) {
        const float4* H0 = reinterpret_cast<const float4*>(g_H + 0ULL * (T_STEPS + 1) * UDIM + UDIM);
        const float4* H1 = reinterpret_cast<const float4*>(g_H + 1ULL * (T_STEPS + 1) * UDIM + UDIM);
        const float4* H2 = reinterpret_cast<const float4*>(g_H + 2ULL * (T_STEPS + 1) * UDIM + UDIM);
        const float4* H3 = reinterpret_cast<const float4*>(g_H + 3ULL * (T_STEPS + 1) * UDIM + UDIM);
        float4 a = H0[i], b = H1[i], cc = H2[i], d = H3[i];
        float4 re, im;
        re.x = a.x - d.x; re.y = a.y - d.y; re.z = a.z - d.z; re.w = a.w - d.w;
        im.x = cc.x + b.x; im.y = cc.y + b.y; im.z = cc.z + b.z; im.w = cc.w + b.w;
        float4* o_re = reinterpret_cast<float4*>(out);
        float4* o_im = reinterpret_cast<float4*>(out + (size_t)T_STEPS * UDIM);
        o_re[i] = re;
        o_im[i] = im;
    }
}

// ---------------------------------------------------------------------------
extern "C" void kernel_launch(void* const* d_in, const int* in_sizes, int n_in,
                              void* d_out, int out_size)
{
    const float* in_real = (const float*)d_in[0];
    const float* in_imag = (const float*)d_in[1];
    const float* states  = (const float*)d_in[2];
    const float* Wr      = (const float*)d_in[3];
    const float* Rr      = (const float*)d_in[4];
    const float* br      = (const float*)d_in[5];
    const float* Wi      = (const float*)d_in[6];
    const float* Ri      = (const float*)d_in[7];
    const float* bi      = (const float*)d_in[8];
    float* out = (float*)d_out;

    init_kernel<<<2, 1024>>>(states);

    dim3 gg(GDIM / BN, (T_STEPS + BM - 1) / BM, 4); // (16, 63, 4)
    gemm_kernel<<<gg, 256>>>(in_real, in_imag, Wr, Wi, br, bi);

    rnn_kernel<<<128, 256>>>(Rr, Ri, states, out);

    combine_kernel<<<(T_STEPS * UDIM / 4 + 255) / 256, 256>>>(out);
}

// round 10
// speedup vs baseline: 2.5461x; 1.3811x over previous
#include <cuda_runtime.h>
#include <cstdint>

// ---------------------------------------------------------------------------
// Problem: 4 coupled LSTMs, B=1, T=8000, F=U=512.
//   pass0: real x Wr/Rr   pass1: real x Wi/Ri
//   pass2: imag x Wr/Rr   pass3: imag x Wi/Ri
//   real_out = h0 - h3 ; imag_out = h2 + h1 ; out_states = final (h,c) per pass
// ---------------------------------------------------------------------------

#define T_STEPS 8000
#define UDIM    512
#define GDIM    2048   // 4*U

// Scratch (allocation-free rule: __device__ globals)
__device__ float    g_xz[4ULL * T_STEPS * GDIM];       // 262 MB: input projections
__device__ float    g_H [4ULL * (T_STEPS + 1) * UDIM]; // 65.5 MB: h history (slot 0 = h_init)
// Barrier flags: ONE 128-byte cache line per CTA (monotonic sequence numbers).
__device__ unsigned g_done[128 * 32];

// ---------------------------------------------------------------------------
// helpers
// ---------------------------------------------------------------------------
__device__ __forceinline__ float2 ffma2(float2 a, float2 b, float2 c) {
    unsigned long long ua = *reinterpret_cast<unsigned long long*>(&a);
    unsigned long long ub = *reinterpret_cast<unsigned long long*>(&b);
    unsigned long long uc = *reinterpret_cast<unsigned long long*>(&c);
    unsigned long long ud;
    asm("fma.rn.f32x2 %0, %1, %2, %3;" : "=l"(ud) : "l"(ua), "l"(ub), "l"(uc));
    return *reinterpret_cast<float2*>(&ud);
}

__device__ __forceinline__ unsigned ld_acq(const unsigned* p) {
    unsigned v;
    asm volatile("ld.acquire.gpu.global.u32 %0, [%1];" : "=r"(v) : "l"(p) : "memory");
    return v;
}
__device__ __forceinline__ void st_rel(unsigned* p, unsigned v) {
    asm volatile("st.release.gpu.global.u32 [%0], %1;" :: "l"(p), "r"(v) : "memory");
}

__device__ __forceinline__ float sigf(float x) {
    // NaN-safe for large |x|
    return 1.0f / (1.0f + __expf(-x));
}
__device__ __forceinline__ float tanh_fast(float x) {
    // 1 - 2/(1+e^{2x}) : saturates cleanly, no inf/inf
    return 1.0f - 2.0f / (1.0f + __expf(2.0f * x));
}

// ---------------------------------------------------------------------------
// init: copy initial h into g_H[p][0][*]
// in_states flat layout [4][512][2] : (..,0)=h, (..,1)=c
// ---------------------------------------------------------------------------
__global__ void init_kernel(const float* __restrict__ states) {
    int idx = blockIdx.x * blockDim.x + threadIdx.x;
    if (idx < 4 * UDIM) {
        int p = idx >> 9, u = idx & 511;
        g_H[(size_t)p * (T_STEPS + 1) * UDIM + u] = states[p * (UDIM * 2) + u * 2 + 0];
    }
}

// ---------------------------------------------------------------------------
// GEMM: xz[p] = X[p] @ W[p] + bias[p], X [8000x512] row-major, W [512x2048]
// 128x128 tile, BK=8, 256 threads, 8x8 micro-tile with f32x2 packed FMA.
// Double-buffered SMEM: one __syncthreads per k-tile, LDG hidden behind FMAs.
// ---------------------------------------------------------------------------
#define BM 128
#define BN 128
#define BK 8

__global__ __launch_bounds__(256, 2) void gemm_kernel(
    const float* __restrict__ Xr, const float* __restrict__ Xi,
    const float* __restrict__ Wr, const float* __restrict__ Wi,
    const float* __restrict__ br, const float* __restrict__ bi)
{
    const int p = blockIdx.z;
    const float* X    = (p >= 2) ? Xi : Xr;
    const float* W    = (p & 1) ? Wi : Wr;
    const float* bias = (p & 1) ? bi : br;
    float* C = g_xz + (size_t)p * T_STEPS * GDIM;

    const int bm = blockIdx.y * BM;
    const int bn = blockIdx.x * BN;

    __shared__ float As[2][BK][BM];
    __shared__ float Bs[2][BK][BN];

    const int tid = threadIdx.x;
    const int tx = tid & 15;   // 0..15 -> col group
    const int ty = tid >> 4;   // 0..15 -> row group

    // global load mapping
    const int arow = tid >> 1;        // 0..127
    const int acol = (tid & 1) * 4;   // 0 or 4
    const int b_r  = tid >> 5;        // 0..7
    const int b_c  = (tid & 31) * 4;  // 0..124

    float2 acc[8][4];
#pragma unroll
    for (int m = 0; m < 8; m++)
#pragma unroll
        for (int n = 0; n < 4; n++) acc[m][n] = make_float2(0.f, 0.f);

    const int m_g = bm + arow;
    const bool a_ok = (m_g < T_STEPS);

    // preload tile 0
    {
        float4 av = make_float4(0.f, 0.f, 0.f, 0.f);
        if (a_ok) av = *reinterpret_cast<const float4*>(X + (size_t)m_g * 512 + acol);
        As[0][acol + 0][arow] = av.x;
        As[0][acol + 1][arow] = av.y;
        As[0][acol + 2][arow] = av.z;
        As[0][acol + 3][arow] = av.w;
        float4 bv = *reinterpret_cast<const float4*>(W + (size_t)b_r * GDIM + bn + b_c);
        *reinterpret_cast<float4*>(&Bs[0][b_r][b_c]) = bv;
    }
    __syncthreads();

    const int NT = 512 / BK; // 64
    for (int tIdx = 0; tIdx < NT; tIdx++) {
        const int buf = tIdx & 1;
        float4 av = make_float4(0.f, 0.f, 0.f, 0.f), bv;
        const bool has_next = (tIdx + 1 < NT);
        if (has_next) {
            const int k0 = (tIdx + 1) * BK;
            if (a_ok) av = *reinterpret_cast<const float4*>(X + (size_t)m_g * 512 + k0 + acol);
            bv = *reinterpret_cast<const float4*>(W + (size_t)(k0 + b_r) * GDIM + bn + b_c);
        }

#pragma unroll
        for (int k = 0; k < BK; k++) {
            float4 a0 = *reinterpret_cast<float4*>(&As[buf][k][ty * 8]);
            float4 a1 = *reinterpret_cast<float4*>(&As[buf][k][ty * 8 + 4]);
            float4 b0 = *reinterpret_cast<float4*>(&Bs[buf][k][tx * 8]);
            float4 b1 = *reinterpret_cast<float4*>(&Bs[buf][k][tx * 8 + 4]);
            float  a[8] = {a0.x, a0.y, a0.z, a0.w, a1.x, a1.y, a1.z, a1.w};
            float2 bp[4] = {make_float2(b0.x, b0.y), make_float2(b0.z, b0.w),
                            make_float2(b1.x, b1.y), make_float2(b1.z, b1.w)};
#pragma unroll
            for (int m = 0; m < 8; m++) {
                float2 am = make_float2(a[m], a[m]);
#pragma unroll
                for (int n = 0; n < 4; n++)
                    acc[m][n] = ffma2(am, bp[n], acc[m][n]);
            }
        }

        if (has_next) {
            const int nb = buf ^ 1;
            As[nb][acol + 0][arow] = av.x;
            As[nb][acol + 1][arow] = av.y;
            As[nb][acol + 2][arow] = av.z;
            As[nb][acol + 3][arow] = av.w;
            *reinterpret_cast<float4*>(&Bs[nb][b_r][b_c]) = bv;
        }
        __syncthreads();
    }

    // store with bias
#pragma unroll
    for (int m = 0; m < 8; m++) {
        int row = bm + ty * 8 + m;
        if (row < T_STEPS) {
#pragma unroll
            for (int n = 0; n < 4; n++) {
                int col = bn + tx * 8 + n * 2;
                float2 r = acc[m][n];
                r.x += bias[col];
                r.y += bias[col + 1];
                *reinterpret_cast<float2*>(C + (size_t)row * GDIM + col) = r;
            }
        }
    }
}

// ---------------------------------------------------------------------------
// Persistent recurrent kernel.
// 128 CTAs x 256 threads. CTAs 0..63: weight set Rr, passes {0,2}.
//                         CTAs 64..127: weight set Ri, passes {1,3}.
// Each CTA owns 8 units; warp w = unit (cta&63)*8+w. Weights live in regs
// as f32x2 pairs (rows r and r+256). Per step: flag barrier within the
// 64-CTA group (padded flag lines), stage h(t) to smem (pre-paired),
// 64 f32x2 FMAs per lane, butterfly reduce, warp0 lanes 0..15 run the gate
// nonlinearities; h(t+1) is consolidated via smem and published by lane 0
// alone (4x STG.128 + st.release — single-thread ordering, no membar).
// ---------------------------------------------------------------------------
__global__ __launch_bounds__(256, 1) void rnn_kernel(
    const float* __restrict__ Rr, const float* __restrict__ Ri,
    const float* __restrict__ states, float* __restrict__ out)
{
    const int cta  = blockIdx.x;
    const int tid  = threadIdx.x;
    const int w    = tid >> 5;
    const int lane = tid & 31;
    const int grp  = cta >> 6;   // 0 = real weight set, 1 = imag weight set
    const int cu   = cta & 63;
    const int unit = cu * 8 + w;

    const float* R = grp ? Ri : Rr;

    __shared__ float2   shp[2][8][32]; // [q][j][lane] = (h[32j+lane], h[32j+256+lane])
    __shared__ float    zsm[8][8];     // [warp][g*2+q]
    __shared__ float    hstage[2][8];  // [q][uj] : h(t+1) staging for lane-0 publish
    __shared__ unsigned sbase;

    // ---- load this warp's weight columns into registers (one-time) ----
    float2 wv[4][8];
#pragma unroll
    for (int g = 0; g < 4; g++) {
        const int col = g * UDIM + unit;
#pragma unroll
        for (int j = 0; j < 8; j++) {
            wv[g][j].x = R[(size_t)(32 * j + lane) * GDIM + col];
            wv[g][j].y = R[(size_t)(32 * j + 256 + lane) * GDIM + col];
        }
    }

    // ---- warp0 per-lane recurrent state ----
    const int q      = lane & 1;
    const int uj     = lane >> 1;
    const int myp    = (grp == 0) ? (q ? 2 : 0) : (q ? 3 : 1);
    const int myunit = cu * 8 + uj;
    float c = 0.f, hlast = 0.f;
    if (w == 0 && lane < 16)
        c = states[myp * (UDIM * 2) + myunit * 2 + 1];

    const int pA = grp ? 1 : 0;
    const int pB = grp ? 3 : 2;

    // barrier base: read own (padded) slot — only our lane0 ever writes it
    if (tid == 0) sbase = ld_acq(&g_done[cta << 5]);
    __syncthreads();
    const unsigned base = sbase;

    const int s_ln = tid & 31;
    const int s_j  = (tid >> 5) & 7;

    float* hA_out = g_H + (size_t)pA * (T_STEPS + 1) * UDIM + (size_t)cu * 8;
    float* hB_out = g_H + (size_t)pB * (T_STEPS + 1) * UDIM + (size_t)cu * 8;

    for (int t = 0; t < T_STEPS; t++) {
        // prefetch xz for this step (independent of the barrier)
        float xzi, xzf, xzg, xzo;
        if (w == 0 && lane < 16) {
            const float* xp = g_xz + ((size_t)myp * T_STEPS + t) * GDIM + myunit;
            xzi = xp[0];
            xzf = xp[UDIM];
            xzg = xp[2 * UDIM];
            xzo = xp[3 * UDIM];
        }

        // wait for all CTAs in this group to have published h(t)
        if (t > 0 && tid < 64) {
            const unsigned tgt = base + (unsigned)t;
            const unsigned* fp = &g_done[(grp * 64 + tid) << 5];
            while (ld_acq(fp) < tgt) { }
        }
        __syncthreads();

        // stage h(t) for both passes into smem, pre-paired for f32x2
        {
            const float* hA = g_H + ((size_t)pA * (T_STEPS + 1) + t) * UDIM;
            const float* hB = g_H + ((size_t)pB * (T_STEPS + 1) + t) * UDIM;
            shp[0][s_j][s_ln] = make_float2(hA[32 * s_j + s_ln], hA[32 * s_j + 256 + s_ln]);
            shp[1][s_j][s_ln] = make_float2(hB[32 * s_j + s_ln], hB[32 * s_j + 256 + s_ln]);
        }
        __syncthreads();

        // z partials: 4 gates x 2 passes, packed over row pairs
        float2 acc[4][2];
#pragma unroll
        for (int g = 0; g < 4; g++) {
            acc[g][0] = make_float2(0.f, 0.f);
            acc[g][1] = make_float2(0.f, 0.f);
        }
#pragma unroll
        for (int j = 0; j < 8; j++) {
            float2 h0 = shp[0][j][lane];
            float2 h1 = shp[1][j][lane];
#pragma unroll
            for (int g = 0; g < 4; g++) {
                acc[g][0] = ffma2(wv[g][j], h0, acc[g][0]);
                acc[g][1] = ffma2(wv[g][j], h1, acc[g][1]);
            }
        }
        float s[8];
#pragma unroll
        for (int g = 0; g < 4; g++) {
            s[g * 2 + 0] = acc[g][0].x + acc[g][0].y;
            s[g * 2 + 1] = acc[g][1].x + acc[g][1].y;
        }
#pragma unroll
        for (int off = 16; off; off >>= 1) {
#pragma unroll
            for (int k = 0; k < 8; k++)
                s[k] += __shfl_xor_sync(0xffffffffu, s[k], off);
        }
        if (lane == 0) {
#pragma unroll
            for (int k = 0; k < 8; k++) zsm[w][k] = s[k];
        }
        __syncthreads();

        // warp0: gates + state update for all 16 (unit,pass) pairs of this CTA
        if (w == 0) {
            if (lane < 16) {
                float zi = zsm[uj][0 + q] + xzi;
                float zf = zsm[uj][2 + q] + xzf;
                float zg = zsm[uj][4 + q] + xzg;
                float zo = zsm[uj][6 + q] + xzo;
                float si = sigf(zi);
                float sf = sigf(zf);
                float tg = tanh_fast(zg);
                float so = sigf(zo);
                c = fmaf(sf, c, si * tg);
                float h = so * tanh_fast(c);
                hlast = h;
                hstage[q][uj] = h;
            }
            __syncwarp();
            if (lane == 0) {
                // lane 0 publishes all 16 h values itself -> single-thread
                // ordering w.r.t. the release store (no membar needed).
                float4 a0 = *reinterpret_cast<float4*>(&hstage[0][0]);
                float4 a1 = *reinterpret_cast<float4*>(&hstage[0][4]);
                float4 b0 = *reinterpret_cast<float4*>(&hstage[1][0]);
                float4 b1 = *reinterpret_cast<float4*>(&hstage[1][4]);
                float* dA = hA_out + (size_t)(t + 1) * UDIM;
                float* dB = hB_out + (size_t)(t + 1) * UDIM;
                *reinterpret_cast<float4*>(dA)     = a0;
                *reinterpret_cast<float4*>(dA + 4) = a1;
                *reinterpret_cast<float4*>(dB)     = b0;
                *reinterpret_cast<float4*>(dB + 4) = b1;
                st_rel(&g_done[cta << 5], base + (unsigned)t + 1u);
            }
        }
    }

    // final states -> out_states region: out[8192000 + p*1024 + u*2 + {0:h,1:c}]
    if (w == 0 && lane < 16) {
        float* os = out + (size_t)2 * T_STEPS * UDIM;
        os[myp * (UDIM * 2) + myunit * 2 + 0] = hlast;
        os[myp * (UDIM * 2) + myunit * 2 + 1] = c;
    }
}

// ---------------------------------------------------------------------------
// combine: real = h0 - h3, imag = h2 + h1  (element i over T*U, float4)
// ---------------------------------------------------------------------------
__global__ void combine_kernel(float* __restrict__ out)
{
    const int i = blockIdx.x * blockDim.x + threadIdx.x; // float4 index
    const int n4 = (T_STEPS * UDIM) / 4;                 // 1,024,000
    if (i < n4) {
        const float4* H0 = reinterpret_cast<const float4*>(g_H + 0ULL * (T_STEPS + 1) * UDIM + UDIM);
        const float4* H1 = reinterpret_cast<const float4*>(g_H + 1ULL * (T_STEPS + 1) * UDIM + UDIM);
        const float4* H2 = reinterpret_cast<const float4*>(g_H + 2ULL * (T_STEPS + 1) * UDIM + UDIM);
        const float4* H3 = reinterpret_cast<const float4*>(g_H + 3ULL * (T_STEPS + 1) * UDIM + UDIM);
        float4 a = H0[i], b = H1[i], cc = H2[i], d = H3[i];
        float4 re, im;
        re.x = a.x - d.x; re.y = a.y - d.y; re.z = a.z - d.z; re.w = a.w - d.w;
        im.x = cc.x + b.x; im.y = cc.y + b.y; im.z = cc.z + b.z; im.w = cc.w + b.w;
        float4* o_re = reinterpret_cast<float4*>(out);
        float4* o_im = reinterpret_cast<float4*>(out + (size_t)T_STEPS * UDIM);
        o_re[i] = re;
        o_im[i] = im;
    }
}

// ---------------------------------------------------------------------------
extern "C" void kernel_launch(void* const* d_in, const int* in_sizes, int n_in,
                              void* d_out, int out_size)
{
    const float* in_real = (const float*)d_in[0];
    const float* in_imag = (const float*)d_in[1];
    const float* states  = (const float*)d_in[2];
    const float* Wr      = (const float*)d_in[3];
    const float* Rr      = (const float*)d_in[4];
    const float* br      = (const float*)d_in[5];
    const float* Wi      = (const float*)d_in[6];
    const float* Ri      = (const float*)d_in[7];
    const float* bi      = (const float*)d_in[8];
    float* out = (float*)d_out;

    init_kernel<<<2, 1024>>>(states);

    dim3 gg(GDIM / BN, (T_STEPS + BM - 1) / BM, 4); // (16, 63, 4)
    gemm_kernel<<<gg, 256>>>(in_real, in_imag, Wr, Wi, br, bi);

    rnn_kernel<<<128, 256>>>(Rr, Ri, states, out);

    combine_kernel<<<(T_STEPS * UDIM / 4 + 255) / 256, 256>>>(out);
}

// round 13
// speedup vs baseline: 2.7017x; 1.0611x over previous
#include <cuda_runtime.h>
#include <cstdint>

// ---------------------------------------------------------------------------
// Problem: 4 coupled LSTMs, B=1, T=8000, F=U=512.
//   pass0: real x Wr/Rr   pass1: real x Wi/Ri
//   pass2: imag x Wr/Rr   pass3: imag x Wi/Ri
//   real_out = h0 - h3 ; imag_out = h2 + h1 ; out_states = final (h,c) per pass
// ---------------------------------------------------------------------------

#define T_STEPS 8000
#define UDIM    512
#define GDIM    2048   // 4*U

// Scratch (allocation-free rule: __device__ globals)
__device__ float g_xz[4ULL * T_STEPS * GDIM];       // 262 MB: input projections
__device__ float g_H [4ULL * (T_STEPS + 1) * UDIM]; // 65.5 MB: h history (slot 0 = h_init)
// Barrier flags: ONE 128-byte cache line per CTA (monotonic sequence numbers).
__device__ unsigned g_done[128 * 32];

// ---------------------------------------------------------------------------
// helpers
// ---------------------------------------------------------------------------
__device__ __forceinline__ float2 ffma2(float2 a, float2 b, float2 c) {
    unsigned long long ua = *reinterpret_cast<unsigned long long*>(&a);
    unsigned long long ub = *reinterpret_cast<unsigned long long*>(&b);
    unsigned long long uc = *reinterpret_cast<unsigned long long*>(&c);
    unsigned long long ud;
    asm("fma.rn.f32x2 %0, %1, %2, %3;" : "=l"(ud) : "l"(ua), "l"(ub), "l"(uc));
    return *reinterpret_cast<float2*>(&ud);
}

__device__ __forceinline__ unsigned ld_acq(const unsigned* p) {
    unsigned v;
    asm volatile("ld.acquire.gpu.global.u32 %0, [%1];" : "=r"(v) : "l"(p) : "memory");
    return v;
}
__device__ __forceinline__ void st_rel(unsigned* p, unsigned v) {
    asm volatile("st.release.gpu.global.u32 [%0], %1;" :: "l"(p), "r"(v) : "memory");
}

__device__ __forceinline__ float sigf(float x) {
    return 1.0f / (1.0f + __expf(-x)); // NaN-safe for large |x|
}
__device__ __forceinline__ float tanh_fast(float x) {
    return 1.0f - 2.0f / (1.0f + __expf(2.0f * x)); // saturates cleanly
}

// ---------------------------------------------------------------------------
// init: copy initial h into g_H[p][0][*]
// in_states flat layout [4][512][2] : (..,0)=h, (..,1)=c
// ---------------------------------------------------------------------------
__global__ void init_kernel(const float* __restrict__ states) {
    int idx = blockIdx.x * blockDim.x + threadIdx.x;
    if (idx < 4 * UDIM) {
        int p = idx >> 9, u = idx & 511;
        g_H[(size_t)p * (T_STEPS + 1) * UDIM + u] = states[p * (UDIM * 2) + u * 2 + 0];
    }
}

// ---------------------------------------------------------------------------
// GEMM: xz[p] = X[p] @ W[p] + bias[p], X [8000x512] row-major, W [512x2048]
// 128x128 tile, BK=8, 256 threads, 8x8 micro-tile, f32x2 FMA, double-buffered.
// ---------------------------------------------------------------------------
#define BM 128
#define BN 128
#define BK 8

__global__ __launch_bounds__(256, 2) void gemm_kernel(
    const float* __restrict__ Xr, const float* __restrict__ Xi,
    const float* __restrict__ Wr, const float* __restrict__ Wi,
    const float* __restrict__ br, const float* __restrict__ bi)
{
    const int p = blockIdx.z;
    const float* X    = (p >= 2) ? Xi : Xr;
    const float* W    = (p & 1) ? Wi : Wr;
    const float* bias = (p & 1) ? bi : br;
    float* C = g_xz + (size_t)p * T_STEPS * GDIM;

    const int bm = blockIdx.y * BM;
    const int bn = blockIdx.x * BN;

    __shared__ float As[2][BK][BM];
    __shared__ float Bs[2][BK][BN];

    const int tid = threadIdx.x;
    const int tx = tid & 15;
    const int ty = tid >> 4;

    const int arow = tid >> 1;
    const int acol = (tid & 1) * 4;
    const int b_r  = tid >> 5;
    const int b_c  = (tid & 31) * 4;

    float2 acc[8][4];
#pragma unroll
    for (int m = 0; m < 8; m++)
#pragma unroll
        for (int n = 0; n < 4; n++) acc[m][n] = make_float2(0.f, 0.f);

    const int m_g = bm + arow;
    const bool a_ok = (m_g < T_STEPS);

    {
        float4 av = make_float4(0.f, 0.f, 0.f, 0.f);
        if (a_ok) av = *reinterpret_cast<const float4*>(X + (size_t)m_g * 512 + acol);
        As[0][acol + 0][arow] = av.x;
        As[0][acol + 1][arow] = av.y;
        As[0][acol + 2][arow] = av.z;
        As[0][acol + 3][arow] = av.w;
        float4 bv = *reinterpret_cast<const float4*>(W + (size_t)b_r * GDIM + bn + b_c);
        *reinterpret_cast<float4*>(&Bs[0][b_r][b_c]) = bv;
    }
    __syncthreads();

    const int NT = 512 / BK; // 64
    for (int tIdx = 0; tIdx < NT; tIdx++) {
        const int buf = tIdx & 1;
        float4 av = make_float4(0.f, 0.f, 0.f, 0.f), bv;
        const bool has_next = (tIdx + 1 < NT);
        if (has_next) {
            const int k0 = (tIdx + 1) * BK;
            if (a_ok) av = *reinterpret_cast<const float4*>(X + (size_t)m_g * 512 + k0 + acol);
            bv = *reinterpret_cast<const float4*>(W + (size_t)(k0 + b_r) * GDIM + bn + b_c);
        }

#pragma unroll
        for (int k = 0; k < BK; k++) {
            float4 a0 = *reinterpret_cast<float4*>(&As[buf][k][ty * 8]);
            float4 a1 = *reinterpret_cast<float4*>(&As[buf][k][ty * 8 + 4]);
            float4 b0 = *reinterpret_cast<float4*>(&Bs[buf][k][tx * 8]);
            float4 b1 = *reinterpret_cast<float4*>(&Bs[buf][k][tx * 8 + 4]);
            float  a[8] = {a0.x, a0.y, a0.z, a0.w, a1.x, a1.y, a1.z, a1.w};
            float2 bp[4] = {make_float2(b0.x, b0.y), make_float2(b0.z, b0.w),
                            make_float2(b1.x, b1.y), make_float2(b1.z, b1.w)};
#pragma unroll
            for (int m = 0; m < 8; m++) {
                float2 am = make_float2(a[m], a[m]);
#pragma unroll
                for (int n = 0; n < 4; n++)
                    acc[m][n] = ffma2(am, bp[n], acc[m][n]);
            }
        }

        if (has_next) {
            const int nb = buf ^ 1;
            As[nb][acol + 0][arow] = av.x;
            As[nb][acol + 1][arow] = av.y;
            As[nb][acol + 2][arow] = av.z;
            As[nb][acol + 3][arow] = av.w;
            *reinterpret_cast<float4*>(&Bs[nb][b_r][b_c]) = bv;
        }
        __syncthreads();
    }

#pragma unroll
    for (int m = 0; m < 8; m++) {
        int row = bm + ty * 8 + m;
        if (row < T_STEPS) {
#pragma unroll
            for (int n = 0; n < 4; n++) {
                int col = bn + tx * 8 + n * 2;
                float2 r = acc[m][n];
                r.x += bias[col];
                r.y += bias[col + 1];
                *reinterpret_cast<float2*>(C + (size_t)row * GDIM + col) = r;
            }
        }
    }
}

// ---------------------------------------------------------------------------
// Persistent recurrent kernel (PROVEN round-10 comm protocol).
// 128 CTAs x 256 threads. CTAs 0..63: Rr, passes {0,2}; CTAs 64..127: Ri, {1,3}.
// Per step: flag barrier within the 64-CTA group (padded flag lines), stage
// h(t) from g_H via ONE float4 load + ONE STS.128 per thread, 64 f32x2 FMAs
// per lane (adjacent-row pairing), value-folding reduce (9 shfls), warp0
// lanes 0..15 run gates; h(t+1) published by lane 0 alone (4x STG.128 +
// st.release — single-thread ordering, no membar).
// ---------------------------------------------------------------------------
__global__ __launch_bounds__(256, 1) void rnn_kernel(
    const float* __restrict__ Rr, const float* __restrict__ Ri,
    const float* __restrict__ states, float* __restrict__ out)
{
    const int cta  = blockIdx.x;
    const int tid  = threadIdx.x;
    const int w    = tid >> 5;
    const int lane = tid & 31;
    const int grp  = cta >> 6;
    const int cu   = cta & 63;
    const int unit = cu * 8 + w;

    const float* R = grp ? Ri : Rr;

    __shared__ __align__(16) float2 shp[2][8][32]; // [q][j][ln] = pair (h[2pi], h[2pi+1]), pi=32j+ln
    __shared__ float    zsm[8][8];     // [warp][g*2+q]
    __shared__ float    hstage[2][8];  // [q][uj] : h(t+1) staging for lane-0 publish
    __shared__ unsigned sbase;

    // ---- weights in registers: ADJACENT-row pairs (2p, 2p+1), p = 32j+lane ----
    float2 wv[4][8];
#pragma unroll
    for (int g = 0; g < 4; g++) {
        const int col = g * UDIM + unit;
#pragma unroll
        for (int j = 0; j < 8; j++) {
            wv[g][j].x = R[(size_t)(64 * j + 2 * lane) * GDIM + col];
            wv[g][j].y = R[(size_t)(64 * j + 2 * lane + 1) * GDIM + col];
        }
    }

    // ---- warp0 per-lane recurrent state ----
    const int q      = lane & 1;
    const int uj     = lane >> 1;
    const int myp    = (grp == 0) ? (q ? 2 : 0) : (q ? 3 : 1);
    const int myunit = cu * 8 + uj;
    float c = 0.f, hlast = 0.f;
    if (w == 0 && lane < 16)
        c = states[myp * (UDIM * 2) + myunit * 2 + 1];

    const int pA = grp ? 1 : 0;
    const int pB = grp ? 3 : 2;

    // barrier base: read own (padded) slot — only our lane0 ever writes it
    if (tid == 0) sbase = ld_acq(&g_done[cta << 5]);
    __syncthreads();
    const unsigned base = sbase;

    // staging assignment: thread tid loads ONE float4 of h for ONE pass
    const int st_q = tid >> 7;       // 0: pass A, 1: pass B
    const int st_m = tid & 127;      // float4 index within the 512-float h vector

    const float* hA_base = g_H + (size_t)pA * (T_STEPS + 1) * UDIM;
    const float* hB_base = g_H + (size_t)pB * (T_STEPS + 1) * UDIM;
    const float* st_src  = (st_q ? hB_base : hA_base) + 4 * st_m;
    float4* const st_dst = reinterpret_cast<float4*>(&shp[st_q][0][0]) + st_m;

    float* hA_out = g_H + (size_t)pA * (T_STEPS + 1) * UDIM + (size_t)cu * 8;
    float* hB_out = g_H + (size_t)pB * (T_STEPS + 1) * UDIM + (size_t)cu * 8;

    for (int t = 0; t < T_STEPS; t++) {
        // prefetch xz for this step (issue before the wait)
        float xzi, xzf, xzg, xzo;
        if (w == 0 && lane < 16) {
            const float* xp = g_xz + ((size_t)myp * T_STEPS + t) * GDIM + myunit;
            xzi = xp[0];
            xzf = xp[UDIM];
            xzg = xp[2 * UDIM];
            xzo = xp[3 * UDIM];
        }

        // wait for all CTAs in this group to have published h(t)
        if (t > 0 && tid < 64) {
            const unsigned tgt = base + (unsigned)t;
            const unsigned* fp = &g_done[(grp * 64 + tid) << 5];
            while (ld_acq(fp) < tgt) { }
        }
        __syncthreads();

        // stage h(t): one LDG.128 + one STS.128 per thread (slot 0 = h_init)
        *st_dst = *reinterpret_cast<const float4*>(st_src + (size_t)t * UDIM);
        __syncthreads();

        // ---- z partials: 4 gates x 2 passes over adjacent-row pairs ----
        float2 acc[4][2];
#pragma unroll
        for (int g = 0; g < 4; g++) {
            acc[g][0] = make_float2(0.f, 0.f);
            acc[g][1] = make_float2(0.f, 0.f);
        }
#pragma unroll
        for (int j = 0; j < 8; j++) {
            float2 h0 = shp[0][j][lane];
            float2 h1 = shp[1][j][lane];
#pragma unroll
            for (int g = 0; g < 4; g++) {
                acc[g][0] = ffma2(wv[g][j], h0, acc[g][0]);
                acc[g][1] = ffma2(wv[g][j], h1, acc[g][1]);
            }
        }
        float s[8];
#pragma unroll
        for (int g = 0; g < 4; g++) {
            s[g * 2 + 0] = acc[g][0].x + acc[g][0].y;
            s[g * 2 + 1] = acc[g][1].x + acc[g][1].y;
        }

        // ---- value-folding reduction: 9 shfls instead of 40 ----
        {
            // round 1: xor 16, fold 8 -> 4
            bool hi = (lane & 16) != 0;
            float t0 = hi ? s[0] : s[4];
            float t1 = hi ? s[1] : s[5];
            float t2 = hi ? s[2] : s[6];
            float t3 = hi ? s[3] : s[7];
            float r0 = __shfl_xor_sync(0xffffffffu, t0, 16);
            float r1 = __shfl_xor_sync(0xffffffffu, t1, 16);
            float r2 = __shfl_xor_sync(0xffffffffu, t2, 16);
            float r3 = __shfl_xor_sync(0xffffffffu, t3, 16);
            s[0] = (hi ? s[4] : s[0]) + r0;
            s[1] = (hi ? s[5] : s[1]) + r1;
            s[2] = (hi ? s[6] : s[2]) + r2;
            s[3] = (hi ? s[7] : s[3]) + r3;
            // round 2: xor 8, fold 4 -> 2
            bool h3 = (lane & 8) != 0;
            t0 = h3 ? s[0] : s[2];
            t1 = h3 ? s[1] : s[3];
            r0 = __shfl_xor_sync(0xffffffffu, t0, 8);
            r1 = __shfl_xor_sync(0xffffffffu, t1, 8);
            s[0] = (h3 ? s[2] : s[0]) + r0;
            s[1] = (h3 ? s[3] : s[1]) + r1;
            // round 3: xor 4, fold 2 -> 1
            bool h2 = (lane & 4) != 0;
            t0 = h2 ? s[0] : s[1];
            r0 = __shfl_xor_sync(0xffffffffu, t0, 4);
            s[0] = (h2 ? s[1] : s[0]) + r0;
            // rounds 4,5: plain butterfly
            s[0] += __shfl_xor_sync(0xffffffffu, s[0], 2);
            s[0] += __shfl_xor_sync(0xffffffffu, s[0], 1);
        }
        if ((lane & 3) == 0) {
            int idx = ((lane >> 4) & 1) * 4 + ((lane >> 3) & 1) * 2 + ((lane >> 2) & 1);
            zsm[w][idx] = s[0];
        }
        __syncthreads();

        // ---- warp0: gates + state update + publish ----
        if (w == 0) {
            if (lane < 16) {
                float zi = zsm[uj][0 + q] + xzi;
                float zf = zsm[uj][2 + q] + xzf;
                float zg = zsm[uj][4 + q] + xzg;
                float zo = zsm[uj][6 + q] + xzo;
                float si = sigf(zi);
                float sf = sigf(zf);
                float tg = tanh_fast(zg);
                float so = sigf(zo);
                c = fmaf(sf, c, si * tg);
                float h = so * tanh_fast(c);
                hlast = h;
                hstage[q][uj] = h;
            }
            __syncwarp();
            if (lane == 0) {
                // lane 0 publishes all 16 h values itself -> single-thread
                // ordering w.r.t. the release store (no membar needed).
                float4 a0 = *reinterpret_cast<float4*>(&hstage[0][0]);
                float4 a1 = *reinterpret_cast<float4*>(&hstage[0][4]);
                float4 b0 = *reinterpret_cast<float4*>(&hstage[1][0]);
                float4 b1 = *reinterpret_cast<float4*>(&hstage[1][4]);
                float* dA = hA_out + (size_t)(t + 1) * UDIM;
                float* dB = hB_out + (size_t)(t + 1) * UDIM;
                *reinterpret_cast<float4*>(dA)     = a0;
                *reinterpret_cast<float4*>(dA + 4) = a1;
                *reinterpret_cast<float4*>(dB)     = b0;
                *reinterpret_cast<float4*>(dB + 4) = b1;
                st_rel(&g_done[cta << 5], base + (unsigned)t + 1u);
            }
        }
    }

    // final states -> out[2*T*U + p*1024 + u*2 + {0:h,1:c}]
    if (w == 0 && lane < 16) {
        float* os = out + (size_t)2 * T_STEPS * UDIM;
        os[myp * (UDIM * 2) + myunit * 2 + 0] = hlast;
        os[myp * (UDIM * 2) + myunit * 2 + 1] = c;
    }
}

// ---------------------------------------------------------------------------
// combine: real = h0 - h3, imag = h2 + h1
// ---------------------------------------------------------------------------
__global__ void combine_kernel(float* __restrict__ out)
{
    const int i = blockIdx.x * blockDim.x + threadIdx.x; // float4 index
    const int n4 = (T_STEPS * UDIM) / 4;
    if (i < n4) {
        const float4* H0 = reinterpret_cast<const float4*>(g_H + 0ULL * (T_STEPS + 1) * UDIM + UDIM);
        const float4* H1 = reinterpret_cast<const float4*>(g_H + 1ULL * (T_STEPS + 1) * UDIM + UDIM);
        const float4* H2 = reinterpret_cast<const float4*>(g_H + 2ULL * (T_STEPS + 1) * UDIM + UDIM);
        const float4* H3 = reinterpret_cast<const float4*>(g_H + 3ULL * (T_STEPS + 1) * UDIM + UDIM);
        float4 a = H0[i], b = H1[i], cc = H2[i], d = H3[i];
        float4 re, im;
        re.x = a.x - d.x; re.y = a.y - d.y; re.z = a.z - d.z; re.w = a.w - d.w;
        im.x = cc.x + b.x; im.y = cc.y + b.y; im.z = cc.z + b.z; im.w = cc.w + b.w;
        float4* o_re = reinterpret_cast<float4*>(out);
        float4* o_im = reinterpret_cast<float4*>(out + (size_t)T_STEPS * UDIM);
        o_re[i] = re;
        o_im[i] = im;
    }
}

// ---------------------------------------------------------------------------
extern "C" void kernel_launch(void* const* d_in, const int* in_sizes, int n_in,
                              void* d_out, int out_size)
{
    const float* in_real = (const float*)d_in[0];
    const float* in_imag = (const float*)d_in[1];
    const float* states  = (const float*)d_in[2];
    const float* Wr      = (const float*)d_in[3];
    const float* Rr      = (const float*)d_in[4];
    const float* br      = (const float*)d_in[5];
    const float* Wi      = (const float*)d_in[6];
    const float* Ri      = (const float*)d_in[7];
    const float* bi      = (const float*)d_in[8];
    float* out = (float*)d_out;

    init_kernel<<<2, 1024>>>(states);

    dim3 gg(GDIM / BN, (T_STEPS + BM - 1) / BM, 4); // (16, 63, 4)
    gemm_kernel<<<gg, 256>>>(in_real, in_imag, Wr, Wi, br, bi);

    rnn_kernel<<<128, 256>>>(Rr, Ri, states, out);

    combine_kernel<<<(T_STEPS * UDIM / 4 + 255) / 256, 256>>>(out);
}

// round 16
// speedup vs baseline: 2.8009x; 1.0367x over previous
#include <cuda_runtime.h>
#include <cstdint>

// ---------------------------------------------------------------------------
// Problem: 4 coupled LSTMs, B=1, T=8000, F=U=512.
//   pass0: real x Wr/Rr   pass1: real x Wi/Ri
//   pass2: imag x Wr/Rr   pass3: imag x Wi/Ri
//   real_out = h0 - h3 ; imag_out = h2 + h1 ; out_states = final (h,c) per pass
// ---------------------------------------------------------------------------

#define T_STEPS 8000
#define UDIM    512
#define GDIM    2048   // 4*U

// Scratch (allocation-free rule: __device__ globals)
__device__ float g_xz[4ULL * T_STEPS * GDIM];       // 262 MB: input projections
__device__ float g_H [4ULL * (T_STEPS + 1) * UDIM]; // 65.5 MB: h history (slot 0 = h_init)
// Aggregated step counters: one per 64-CTA group, own 128B line each.
// Zeroed by init_kernel every replay (stream-ordered before rnn_kernel).
__device__ unsigned g_count[2 * 32];

// ---------------------------------------------------------------------------
// helpers
// ---------------------------------------------------------------------------
__device__ __forceinline__ float2 ffma2(float2 a, float2 b, float2 c) {
    unsigned long long ua = *reinterpret_cast<unsigned long long*>(&a);
    unsigned long long ub = *reinterpret_cast<unsigned long long*>(&b);
    unsigned long long uc = *reinterpret_cast<unsigned long long*>(&c);
    unsigned long long ud;
    asm("fma.rn.f32x2 %0, %1, %2, %3;" : "=l"(ud) : "l"(ua), "l"(ub), "l"(uc));
    return *reinterpret_cast<float2*>(&ud);
}

__device__ __forceinline__ unsigned ld_acq(const unsigned* p) {
    unsigned v;
    asm volatile("ld.acquire.gpu.global.u32 %0, [%1];" : "=r"(v) : "l"(p) : "memory");
    return v;
}
__device__ __forceinline__ void red_rel_add(unsigned* p, unsigned v) {
    asm volatile("red.release.gpu.global.add.u32 [%0], %1;" :: "l"(p), "r"(v) : "memory");
}

__device__ __forceinline__ float sigf(float x) {
    return 1.0f / (1.0f + __expf(-x)); // NaN-safe for large |x|
}
__device__ __forceinline__ float tanh_fast(float x) {
    return 1.0f - 2.0f / (1.0f + __expf(2.0f * x)); // saturates cleanly
}

// ---------------------------------------------------------------------------
// init: copy initial h into g_H[p][0][*]; zero the step counters.
// in_states flat layout [4][512][2] : (..,0)=h, (..,1)=c
// ---------------------------------------------------------------------------
__global__ void init_kernel(const float* __restrict__ states) {
    int idx = blockIdx.x * blockDim.x + threadIdx.x;
    if (idx < 4 * UDIM) {
        int p = idx >> 9, u = idx & 511;
        g_H[(size_t)p * (T_STEPS + 1) * UDIM + u] = states[p * (UDIM * 2) + u * 2 + 0];
    }
    if (idx < 2) g_count[idx * 32] = 0u;
}

// ---------------------------------------------------------------------------
// GEMM: xz[p] = X[p] @ W[p] + bias[p], X [8000x512] row-major, W [512x2048]
// 128x128 tile, BK=8, 256 threads, 8x8 micro-tile, f32x2 FMA, double-buffered.
// ---------------------------------------------------------------------------
#define BM 128
#define BN 128
#define BK 8

__global__ __launch_bounds__(256, 2) void gemm_kernel(
    const float* __restrict__ Xr, const float* __restrict__ Xi,
    const float* __restrict__ Wr, const float* __restrict__ Wi,
    const float* __restrict__ br, const float* __restrict__ bi)
{
    const int p = blockIdx.z;
    const float* X    = (p >= 2) ? Xi : Xr;
    const float* W    = (p & 1) ? Wi : Wr;
    const float* bias = (p & 1) ? bi : br;
    float* C = g_xz + (size_t)p * T_STEPS * GDIM;

    const int bm = blockIdx.y * BM;
    const int bn = blockIdx.x * BN;

    __shared__ float As[2][BK][BM];
    __shared__ float Bs[2][BK][BN];

    const int tid = threadIdx.x;
    const int tx = tid & 15;
    const int ty = tid >> 4;

    const int arow = tid >> 1;
    const int acol = (tid & 1) * 4;
    const int b_r  = tid >> 5;
    const int b_c  = (tid & 31) * 4;

    float2 acc[8][4];
#pragma unroll
    for (int m = 0; m < 8; m++)
#pragma unroll
        for (int n = 0; n < 4; n++) acc[m][n] = make_float2(0.f, 0.f);

    const int m_g = bm + arow;
    const bool a_ok = (m_g < T_STEPS);

    {
        float4 av = make_float4(0.f, 0.f, 0.f, 0.f);
        if (a_ok) av = *reinterpret_cast<const float4*>(X + (size_t)m_g * 512 + acol);
        As[0][acol + 0][arow] = av.x;
        As[0][acol + 1][arow] = av.y;
        As[0][acol + 2][arow] = av.z;
        As[0][acol + 3][arow] = av.w;
        float4 bv = *reinterpret_cast<const float4*>(W + (size_t)b_r * GDIM + bn + b_c);
        *reinterpret_cast<float4*>(&Bs[0][b_r][b_c]) = bv;
    }
    __syncthreads();

    const int NT = 512 / BK; // 64
    for (int tIdx = 0; tIdx < NT; tIdx++) {
        const int buf = tIdx & 1;
        float4 av = make_float4(0.f, 0.f, 0.f, 0.f), bv;
        const bool has_next = (tIdx + 1 < NT);
        if (has_next) {
            const int k0 = (tIdx + 1) * BK;
            if (a_ok) av = *reinterpret_cast<const float4*>(X + (size_t)m_g * 512 + k0 + acol);
            bv = *reinterpret_cast<const float4*>(W + (size_t)(k0 + b_r) * GDIM + bn + b_c);
        }

#pragma unroll
        for (int k = 0; k < BK; k++) {
            float4 a0 = *reinterpret_cast<float4*>(&As[buf][k][ty * 8]);
            float4 a1 = *reinterpret_cast<float4*>(&As[buf][k][ty * 8 + 4]);
            float4 b0 = *reinterpret_cast<float4*>(&Bs[buf][k][tx * 8]);
            float4 b1 = *reinterpret_cast<float4*>(&Bs[buf][k][tx * 8 + 4]);
            float  a[8] = {a0.x, a0.y, a0.z, a0.w, a1.x, a1.y, a1.z, a1.w};
            float2 bp[4] = {make_float2(b0.x, b0.y), make_float2(b0.z, b0.w),
                            make_float2(b1.x, b1.y), make_float2(b1.z, b1.w)};
#pragma unroll
            for (int m = 0; m < 8; m++) {
                float2 am = make_float2(a[m], a[m]);
#pragma unroll
                for (int n = 0; n < 4; n++)
                    acc[m][n] = ffma2(am, bp[n], acc[m][n]);
            }
        }

        if (has_next) {
            const int nb = buf ^ 1;
            As[nb][acol + 0][arow] = av.x;
            As[nb][acol + 1][arow] = av.y;
            As[nb][acol + 2][arow] = av.z;
            As[nb][acol + 3][arow] = av.w;
            *reinterpret_cast<float4*>(&Bs[nb][b_r][b_c]) = bv;
        }
        __syncthreads();
    }

#pragma unroll
    for (int m = 0; m < 8; m++) {
        int row = bm + ty * 8 + m;
        if (row < T_STEPS) {
#pragma unroll
            for (int n = 0; n < 4; n++) {
                int col = bn + tx * 8 + n * 2;
                float2 r = acc[m][n];
                r.x += bias[col];
                r.y += bias[col + 1];
                *reinterpret_cast<float2*>(C + (size_t)row * GDIM + col) = r;
            }
        }
    }
}

// ---------------------------------------------------------------------------
// Persistent recurrent kernel — round-13 skeleton + aggregated-counter barrier.
// 128 CTAs x 256 threads. CTAs 0..63: Rr, passes {0,2}; CTAs 64..127: Ri, {1,3}.
//
// Per step:
//   tid0 polls ONE counter line: count >= 64*t  (no per-producer max)
//   __syncthreads
//   stage h(t): one LDG.128 + one STS.128 per thread
//   __syncthreads
//   FMA (64 f32x2/lane) + value-folding reduce (9 shfls) + zsm
//   __syncthreads
//   warp0: gates; lane0 publishes h(t+1) (4x STG.128) then
//          red.release.gpu.add(counter, 1)  — release orders the h stores.
//
// Counter soundness: a CTA can only publish step t+1 after observing
// count >= 64*t, so count stays < 64*t until the last step-t publish.
// Counter is zeroed by init_kernel each replay (graph is stream-ordered).
// ---------------------------------------------------------------------------
__global__ __launch_bounds__(256, 1) void rnn_kernel(
    const float* __restrict__ Rr, const float* __restrict__ Ri,
    const float* __restrict__ states, float* __restrict__ out)
{
    const int cta  = blockIdx.x;
    const int tid  = threadIdx.x;
    const int w    = tid >> 5;
    const int lane = tid & 31;
    const int grp  = cta >> 6;
    const int cu   = cta & 63;
    const int unit = cu * 8 + w;

    const float* R = grp ? Ri : Rr;

    __shared__ __align__(16) float2 shp[2][8][32]; // [q][j][ln] = (h[2pi], h[2pi+1]), pi=32j+ln
    __shared__ float zsm[8][8];                    // [warp][g*2+q]
    __shared__ __align__(16) float hstage[2][8];   // [q][uj] : h(t+1) staging for lane-0 publish

    // ---- weights in registers: ADJACENT-row pairs (2p, 2p+1), p = 32j+lane ----
    float2 wv[4][8];
#pragma unroll
    for (int g = 0; g < 4; g++) {
        const int col = g * UDIM + unit;
#pragma unroll
        for (int j = 0; j < 8; j++) {
            wv[g][j].x = R[(size_t)(64 * j + 2 * lane) * GDIM + col];
            wv[g][j].y = R[(size_t)(64 * j + 2 * lane + 1) * GDIM + col];
        }
    }

    // ---- warp0 per-lane recurrent state ----
    const int q      = lane & 1;
    const int uj     = lane >> 1;
    const int myp    = (grp == 0) ? (q ? 2 : 0) : (q ? 3 : 1);
    const int myunit = cu * 8 + uj;
    float c = 0.f, hlast = 0.f;
    if (w == 0 && lane < 16)
        c = states[myp * (UDIM * 2) + myunit * 2 + 1];

    const int pA = grp ? 1 : 0;
    const int pB = grp ? 3 : 2;

    unsigned* const cnt = &g_count[grp * 32];

    // staging assignment: thread tid loads ONE float4 of h for ONE pass
    const int st_q = tid >> 7;       // 0: pass A, 1: pass B
    const int st_m = tid & 127;      // float4 index within the 512-float h vector

    const float* hA_base = g_H + (size_t)pA * (T_STEPS + 1) * UDIM;
    const float* hB_base = g_H + (size_t)pB * (T_STEPS + 1) * UDIM;
    const float* st_src  = (st_q ? hB_base : hA_base) + 4 * st_m;
    float4* const st_dst = reinterpret_cast<float4*>(&shp[st_q][0][0]) + st_m;

    float* hA_out = g_H + (size_t)pA * (T_STEPS + 1) * UDIM + (size_t)cu * 8;
    float* hB_out = g_H + (size_t)pB * (T_STEPS + 1) * UDIM + (size_t)cu * 8;

    for (int t = 0; t < T_STEPS; t++) {
        // prefetch xz for this step (issue before the wait)
        float xzi, xzf, xzg, xzo;
        if (w == 0 && lane < 16) {
            const float* xp = g_xz + ((size_t)myp * T_STEPS + t) * GDIM + myunit;
            xzi = xp[0];
            xzf = xp[UDIM];
            xzg = xp[2 * UDIM];
            xzo = xp[3 * UDIM];
        }

        // ---- wait: single aggregated counter, one poller per CTA ----
        if (t > 0 && tid == 0) {
            const unsigned tgt = (unsigned)t * 64u;
            while (ld_acq(cnt) < tgt) { }
        }
        __syncthreads();

        // stage h(t): one LDG.128 + one STS.128 per thread (slot 0 = h_init)
        *st_dst = *reinterpret_cast<const float4*>(st_src + (size_t)t * UDIM);
        __syncthreads();

        // ---- z partials: 4 gates x 2 passes over adjacent-row pairs ----
        float2 acc[4][2];
#pragma unroll
        for (int g = 0; g < 4; g++) {
            acc[g][0] = make_float2(0.f, 0.f);
            acc[g][1] = make_float2(0.f, 0.f);
        }
#pragma unroll
        for (int j = 0; j < 8; j++) {
            float2 h0 = shp[0][j][lane];
            float2 h1 = shp[1][j][lane];
#pragma unroll
            for (int g = 0; g < 4; g++) {
                acc[g][0] = ffma2(wv[g][j], h0, acc[g][0]);
                acc[g][1] = ffma2(wv[g][j], h1, acc[g][1]);
            }
        }
        float s[8];
#pragma unroll
        for (int g = 0; g < 4; g++) {
            s[g * 2 + 0] = acc[g][0].x + acc[g][0].y;
            s[g * 2 + 1] = acc[g][1].x + acc[g][1].y;
        }

        // ---- value-folding reduction: 9 shfls ----
        {
            bool hi = (lane & 16) != 0;
            float t0 = hi ? s[0] : s[4];
            float t1 = hi ? s[1] : s[5];
            float t2 = hi ? s[2] : s[6];
            float t3 = hi ? s[3] : s[7];
            float r0 = __shfl_xor_sync(0xffffffffu, t0, 16);
            float r1 = __shfl_xor_sync(0xffffffffu, t1, 16);
            float r2 = __shfl_xor_sync(0xffffffffu, t2, 16);
            float r3 = __shfl_xor_sync(0xffffffffu, t3, 16);
            s[0] = (hi ? s[4] : s[0]) + r0;
            s[1] = (hi ? s[5] : s[1]) + r1;
            s[2] = (hi ? s[6] : s[2]) + r2;
            s[3] = (hi ? s[7] : s[3]) + r3;
            bool h3 = (lane & 8) != 0;
            t0 = h3 ? s[0] : s[2];
            t1 = h3 ? s[1] : s[3];
            r0 = __shfl_xor_sync(0xffffffffu, t0, 8);
            r1 = __shfl_xor_sync(0xffffffffu, t1, 8);
            s[0] = (h3 ? s[2] : s[0]) + r0;
            s[1] = (h3 ? s[3] : s[1]) + r1;
            bool h2 = (lane & 4) != 0;
            t0 = h2 ? s[0] : s[1];
            r0 = __shfl_xor_sync(0xffffffffu, t0, 4);
            s[0] = (h2 ? s[1] : s[0]) + r0;
            s[0] += __shfl_xor_sync(0xffffffffu, s[0], 2);
            s[0] += __shfl_xor_sync(0xffffffffu, s[0], 1);
        }
        if ((lane & 3) == 0) {
            int idx = ((lane >> 4) & 1) * 4 + ((lane >> 3) & 1) * 2 + ((lane >> 2) & 1);
            zsm[w][idx] = s[0];
        }
        __syncthreads();

        // ---- warp0: gates + state update + publish ----
        if (w == 0) {
            if (lane < 16) {
                float zi = zsm[uj][0 + q] + xzi;
                float zf = zsm[uj][2 + q] + xzf;
                float zg = zsm[uj][4 + q] + xzg;
                float zo = zsm[uj][6 + q] + xzo;
                float si = sigf(zi);
                float sf = sigf(zf);
                float tg = tanh_fast(zg);
                float so = sigf(zo);
                c = fmaf(sf, c, si * tg);
                float h = so * tanh_fast(c);
                hlast = h;
                hstage[q][uj] = h;
            }
            __syncwarp();
            if (lane == 0) {
                // lane 0 publishes all 16 h values itself, then one
                // red.release increment — the release orders the h stores.
                float4 a0 = *reinterpret_cast<float4*>(&hstage[0][0]);
                float4 a1 = *reinterpret_cast<float4*>(&hstage[0][4]);
                float4 b0 = *reinterpret_cast<float4*>(&hstage[1][0]);
                float4 b1 = *reinterpret_cast<float4*>(&hstage[1][4]);
                float* dA = hA_out + (size_t)(t + 1) * UDIM;
                float* dB = hB_out + (size_t)(t + 1) * UDIM;
                *reinterpret_cast<float4*>(dA)     = a0;
                *reinterpret_cast<float4*>(dA + 4) = a1;
                *reinterpret_cast<float4*>(dB)     = b0;
                *reinterpret_cast<float4*>(dB + 4) = b1;
                red_rel_add(cnt, 1u);
            }
        }
    }

    // final states -> out[2*T*U + p*1024 + u*2 + {0:h,1:c}]
    if (w == 0 && lane < 16) {
        float* os = out + (size_t)2 * T_STEPS * UDIM;
        os[myp * (UDIM * 2) + myunit * 2 + 0] = hlast;
        os[myp * (UDIM * 2) + myunit * 2 + 1] = c;
    }
}

// ---------------------------------------------------------------------------
// combine: real = h0 - h3, imag = h2 + h1
// ---------------------------------------------------------------------------
__global__ void combine_kernel(float* __restrict__ out)
{
    const int i = blockIdx.x * blockDim.x + threadIdx.x; // float4 index
    const int n4 = (T_STEPS * UDIM) / 4;
    if (i < n4) {
        const float4* H0 = reinterpret_cast<const float4*>(g_H + 0ULL * (T_STEPS + 1) * UDIM + UDIM);
        const float4* H1 = reinterpret_cast<const float4*>(g_H + 1ULL * (T_STEPS + 1) * UDIM + UDIM);
        const float4* H2 = reinterpret_cast<const float4*>(g_H + 2ULL * (T_STEPS + 1) * UDIM + UDIM);
        const float4* H3 = reinterpret_cast<const float4*>(g_H + 3ULL * (T_STEPS + 1) * UDIM + UDIM);
        float4 a = H0[i], b = H1[i], cc = H2[i], d = H3[i];
        float4 re, im;
        re.x = a.x - d.x; re.y = a.y - d.y; re.z = a.z - d.z; re.w = a.w - d.w;
        im.x = cc.x + b.x; im.y = cc.y + b.y; im.z = cc.z + b.z; im.w = cc.w + b.w;
        float4* o_re = reinterpret_cast<float4*>(out);
        float4* o_im = reinterpret_cast<float4*>(out + (size_t)T_STEPS * UDIM);
        o_re[i] = re;
        o_im[i] = im;
    }
}

// ---------------------------------------------------------------------------
extern "C" void kernel_launch(void* const* d_in, const int* in_sizes, int n_in,
                              void* d_out, int out_size)
{
    const float* in_real = (const float*)d_in[0];
    const float* in_imag = (const float*)d_in[1];
    const float* states  = (const float*)d_in[2];
    const float* Wr      = (const float*)d_in[3];
    const float* Rr      = (const float*)d_in[4];
    const float* br      = (const float*)d_in[5];
    const float* Wi      = (const float*)d_in[6];
    const float* Ri      = (const float*)d_in[7];
    const float* bi      = (const float*)d_in[8];
    float* out = (float*)d_out;

    init_kernel<<<2, 1024>>>(states);

    dim3 gg(GDIM / BN, (T_STEPS + BM - 1) / BM, 4); // (16, 63, 4)
    gemm_kernel<<<gg, 256>>>(in_real, in_imag, Wr, Wi, br, bi);

    rnn_kernel<<<128, 256>>>(Rr, Ri, states, out);

    combine_kernel<<<(T_STEPS * UDIM / 4 + 255) / 256, 256>>>(out);
}

// round 17
// speedup vs baseline: 2.8971x; 1.0344x over previous
#include <cuda_runtime.h>
#include <cstdint>

// ---------------------------------------------------------------------------
// Problem: 4 coupled LSTMs, B=1, T=8000, F=U=512.
//   pass0: real x Wr/Rr   pass1: real x Wi/Ri
//   pass2: imag x Wr/Rr   pass3: imag x Wi/Ri
//   real_out = h0 - h3 ; imag_out = h2 + h1 ; out_states = final (h,c) per pass
// ---------------------------------------------------------------------------

#define T_STEPS 8000
#define UDIM    512
#define GDIM    2048   // 4*U

// Scratch (allocation-free rule: __device__ globals)
__device__ float g_xz[4ULL * T_STEPS * GDIM];       // 262 MB: input projections
__device__ float g_H [4ULL * (T_STEPS + 1) * UDIM]; // 65.5 MB: h history (slot 0 = h_init)
// Aggregated step counters: one per 64-CTA group, own 128B line each.
// Zeroed by init_kernel every replay (stream-ordered before rnn_kernel).
__device__ unsigned g_count[2 * 32];

// ---------------------------------------------------------------------------
// helpers
// ---------------------------------------------------------------------------
__device__ __forceinline__ float2 ffma2(float2 a, float2 b, float2 c) {
    unsigned long long ua = *reinterpret_cast<unsigned long long*>(&a);
    unsigned long long ub = *reinterpret_cast<unsigned long long*>(&b);
    unsigned long long uc = *reinterpret_cast<unsigned long long*>(&c);
    unsigned long long ud;
    asm("fma.rn.f32x2 %0, %1, %2, %3;" : "=l"(ud) : "l"(ua), "l"(ub), "l"(uc));
    return *reinterpret_cast<float2*>(&ud);
}

__device__ __forceinline__ unsigned ld_acq(const unsigned* p) {
    unsigned v;
    asm volatile("ld.acquire.gpu.global.u32 %0, [%1];" : "=r"(v) : "l"(p) : "memory");
    return v;
}
__device__ __forceinline__ void red_rel_add(unsigned* p, unsigned v) {
    asm volatile("red.release.gpu.global.add.u32 [%0], %1;" :: "l"(p), "r"(v) : "memory");
}

__device__ __forceinline__ float sigf(float x) {
    return 1.0f / (1.0f + __expf(-x)); // NaN-safe for large |x|
}
__device__ __forceinline__ float tanh_fast(float x) {
    return 1.0f - 2.0f / (1.0f + __expf(2.0f * x)); // saturates cleanly
}

// ---------------------------------------------------------------------------
// init: copy initial h into g_H[p][0][*]; zero the step counters.
// in_states flat layout [4][512][2] : (..,0)=h, (..,1)=c
// ---------------------------------------------------------------------------
__global__ void init_kernel(const float* __restrict__ states) {
    int idx = blockIdx.x * blockDim.x + threadIdx.x;
    if (idx < 4 * UDIM) {
        int p = idx >> 9, u = idx & 511;
        g_H[(size_t)p * (T_STEPS + 1) * UDIM + u] = states[p * (UDIM * 2) + u * 2 + 0];
    }
    if (idx < 2) g_count[idx * 32] = 0u;
}

// ---------------------------------------------------------------------------
// GEMM: xz[p] = X[p] @ W[p] + bias[p], X [8000x512] row-major, W [512x2048]
// 128x128 tile, BK=8, 256 threads, 8x8 micro-tile, f32x2 FMA, double-buffered.
// ---------------------------------------------------------------------------
#define BM 128
#define BN 128
#define BK 8

__global__ __launch_bounds__(256, 2) void gemm_kernel(
    const float* __restrict__ Xr, const float* __restrict__ Xi,
    const float* __restrict__ Wr, const float* __restrict__ Wi,
    const float* __restrict__ br, const float* __restrict__ bi)
{
    const int p = blockIdx.z;
    const float* X    = (p >= 2) ? Xi : Xr;
    const float* W    = (p & 1) ? Wi : Wr;
    const float* bias = (p & 1) ? bi : br;
    float* C = g_xz + (size_t)p * T_STEPS * GDIM;

    const int bm = blockIdx.y * BM;
    const int bn = blockIdx.x * BN;

    __shared__ float As[2][BK][BM];
    __shared__ float Bs[2][BK][BN];

    const int tid = threadIdx.x;
    const int tx = tid & 15;
    const int ty = tid >> 4;

    const int arow = tid >> 1;
    const int acol = (tid & 1) * 4;
    const int b_r  = tid >> 5;
    const int b_c  = (tid & 31) * 4;

    float2 acc[8][4];
#pragma unroll
    for (int m = 0; m < 8; m++)
#pragma unroll
        for (int n = 0; n < 4; n++) acc[m][n] = make_float2(0.f, 0.f);

    const int m_g = bm + arow;
    const bool a_ok = (m_g < T_STEPS);

    {
        float4 av = make_float4(0.f, 0.f, 0.f, 0.f);
        if (a_ok) av = *reinterpret_cast<const float4*>(X + (size_t)m_g * 512 + acol);
        As[0][acol + 0][arow] = av.x;
        As[0][acol + 1][arow] = av.y;
        As[0][acol + 2][arow] = av.z;
        As[0][acol + 3][arow] = av.w;
        float4 bv = *reinterpret_cast<const float4*>(W + (size_t)b_r * GDIM + bn + b_c);
        *reinterpret_cast<float4*>(&Bs[0][b_r][b_c]) = bv;
    }
    __syncthreads();

    const int NT = 512 / BK; // 64
    for (int tIdx = 0; tIdx < NT; tIdx++) {
        const int buf = tIdx & 1;
        float4 av = make_float4(0.f, 0.f, 0.f, 0.f), bv;
        const bool has_next = (tIdx + 1 < NT);
        if (has_next) {
            const int k0 = (tIdx + 1) * BK;
            if (a_ok) av = *reinterpret_cast<const float4*>(X + (size_t)m_g * 512 + k0 + acol);
            bv = *reinterpret_cast<const float4*>(W + (size_t)(k0 + b_r) * GDIM + bn + b_c);
        }

#pragma unroll
        for (int k = 0; k < BK; k++) {
            float4 a0 = *reinterpret_cast<float4*>(&As[buf][k][ty * 8]);
            float4 a1 = *reinterpret_cast<float4*>(&As[buf][k][ty * 8 + 4]);
            float4 b0 = *reinterpret_cast<float4*>(&Bs[buf][k][tx * 8]);
            float4 b1 = *reinterpret_cast<float4*>(&Bs[buf][k][tx * 8 + 4]);
            float  a[8] = {a0.x, a0.y, a0.z, a0.w, a1.x, a1.y, a1.z, a1.w};
            float2 bp[4] = {make_float2(b0.x, b0.y), make_float2(b0.z, b0.w),
                            make_float2(b1.x, b1.y), make_float2(b1.z, b1.w)};
#pragma unroll
            for (int m = 0; m < 8; m++) {
                float2 am = make_float2(a[m], a[m]);
#pragma unroll
                for (int n = 0; n < 4; n++)
                    acc[m][n] = ffma2(am, bp[n], acc[m][n]);
            }
        }

        if (has_next) {
            const int nb = buf ^ 1;
            As[nb][acol + 0][arow] = av.x;
            As[nb][acol + 1][arow] = av.y;
            As[nb][acol + 2][arow] = av.z;
            As[nb][acol + 3][arow] = av.w;
            *reinterpret_cast<float4*>(&Bs[nb][b_r][b_c]) = bv;
        }
        __syncthreads();
    }

#pragma unroll
    for (int m = 0; m < 8; m++) {
        int row = bm + ty * 8 + m;
        if (row < T_STEPS) {
#pragma unroll
            for (int n = 0; n < 4; n++) {
                int col = bn + tx * 8 + n * 2;
                float2 r = acc[m][n];
                r.x += bias[col];
                r.y += bias[col + 1];
                *reinterpret_cast<float2*>(C + (size_t)row * GDIM + col) = r;
            }
        }
    }
}

// ---------------------------------------------------------------------------
// Persistent recurrent kernel — round-13 skeleton + aggregated-counter barrier.
// 128 CTAs x 256 threads. CTAs 0..63: Rr, passes {0,2}; CTAs 64..127: Ri, {1,3}.
//
// Per step:
//   tid0 polls ONE counter line: count >= 64*t  (no per-producer max)
//   __syncthreads
//   stage h(t): one LDG.128 + one STS.128 per thread
//   __syncthreads
//   FMA (64 f32x2/lane) + value-folding reduce (9 shfls) + zsm
//   __syncthreads
//   warp0: gates; lane0 publishes h(t+1) (4x STG.128) then
//          red.release.gpu.add(counter, 1)  — release orders the h stores.
//
// Counter soundness: a CTA can only publish step t+1 after observing
// count >= 64*t, so count stays < 64*t until the last step-t publish.
// Counter is zeroed by init_kernel each replay (graph is stream-ordered).
// ---------------------------------------------------------------------------
__global__ __launch_bounds__(256, 1) void rnn_kernel(
    const float* __restrict__ Rr, const float* __restrict__ Ri,
    const float* __restrict__ states, float* __restrict__ out)
{
    const int cta  = blockIdx.x;
    const int tid  = threadIdx.x;
    const int w    = tid >> 5;
    const int lane = tid & 31;
    const int grp  = cta >> 6;
    const int cu   = cta & 63;
    const int unit = cu * 8 + w;

    const float* R = grp ? Ri : Rr;

    __shared__ __align__(16) float2 shp[2][8][32]; // [q][j][ln] = (h[2pi], h[2pi+1]), pi=32j+ln
    __shared__ float zsm[8][8];                    // [warp][g*2+q]
    __shared__ __align__(16) float hstage[2][8];   // [q][uj] : h(t+1) staging for lane-0 publish

    // ---- weights in registers: ADJACENT-row pairs (2p, 2p+1), p = 32j+lane ----
    float2 wv[4][8];
#pragma unroll
    for (int g = 0; g < 4; g++) {
        const int col = g * UDIM + unit;
#pragma unroll
        for (int j = 0; j < 8; j++) {
            wv[g][j].x = R[(size_t)(64 * j + 2 * lane) * GDIM + col];
            wv[g][j].y = R[(size_t)(64 * j + 2 * lane + 1) * GDIM + col];
        }
    }

    // ---- warp0 per-lane recurrent state ----
    const int q      = lane & 1;
    const int uj     = lane >> 1;
    const int myp    = (grp == 0) ? (q ? 2 : 0) : (q ? 3 : 1);
    const int myunit = cu * 8 + uj;
    float c = 0.f, hlast = 0.f;
    if (w == 0 && lane < 16)
        c = states[myp * (UDIM * 2) + myunit * 2 + 1];

    const int pA = grp ? 1 : 0;
    const int pB = grp ? 3 : 2;

    unsigned* const cnt = &g_count[grp * 32];

    // staging assignment: thread tid loads ONE float4 of h for ONE pass
    const int st_q = tid >> 7;       // 0: pass A, 1: pass B
    const int st_m = tid & 127;      // float4 index within the 512-float h vector

    const float* hA_base = g_H + (size_t)pA * (T_STEPS + 1) * UDIM;
    const float* hB_base = g_H + (size_t)pB * (T_STEPS + 1) * UDIM;
    const float* st_src  = (st_q ? hB_base : hA_base) + 4 * st_m;
    float4* const st_dst = reinterpret_cast<float4*>(&shp[st_q][0][0]) + st_m;

    float* hA_out = g_H + (size_t)pA * (T_STEPS + 1) * UDIM + (size_t)cu * 8;
    float* hB_out = g_H + (size_t)pB * (T_STEPS + 1) * UDIM + (size_t)cu * 8;

    for (int t = 0; t < T_STEPS; t++) {
        // prefetch xz for this step (issue before the wait)
        float xzi, xzf, xzg, xzo;
        if (w == 0 && lane < 16) {
            const float* xp = g_xz + ((size_t)myp * T_STEPS + t) * GDIM + myunit;
            xzi = xp[0];
            xzf = xp[UDIM];
            xzg = xp[2 * UDIM];
            xzo = xp[3 * UDIM];
        }

        // ---- wait: single aggregated counter, one poller per CTA ----
        if (t > 0 && tid == 0) {
            const unsigned tgt = (unsigned)t * 64u;
            while (ld_acq(cnt) < tgt) { }
        }
        __syncthreads();

        // stage h(t): one LDG.128 + one STS.128 per thread (slot 0 = h_init)
        *st_dst = *reinterpret_cast<const float4*>(st_src + (size_t)t * UDIM);
        __syncthreads();

        // ---- z partials: 4 gates x 2 passes over adjacent-row pairs ----
        float2 acc[4][2];
#pragma unroll
        for (int g = 0; g < 4; g++) {
            acc[g][0] = make_float2(0.f, 0.f);
            acc[g][1] = make_float2(0.f, 0.f);
        }
#pragma unroll
        for (int j = 0; j < 8; j++) {
            float2 h0 = shp[0][j][lane];
            float2 h1 = shp[1][j][lane];
#pragma unroll
            for (int g = 0; g < 4; g++) {
                acc[g][0] = ffma2(wv[g][j], h0, acc[g][0]);
                acc[g][1] = ffma2(wv[g][j], h1, acc[g][1]);
            }
        }
        float s[8];
#pragma unroll
        for (int g = 0; g < 4; g++) {
            s[g * 2 + 0] = acc[g][0].x + acc[g][0].y;
            s[g * 2 + 1] = acc[g][1].x + acc[g][1].y;
        }

        // ---- value-folding reduction: 9 shfls ----
        {
            bool hi = (lane & 16) != 0;
            float t0 = hi ? s[0] : s[4];
            float t1 = hi ? s[1] : s[5];
            float t2 = hi ? s[2] : s[6];
            float t3 = hi ? s[3] : s[7];
            float r0 = __shfl_xor_sync(0xffffffffu, t0, 16);
            float r1 = __shfl_xor_sync(0xffffffffu, t1, 16);
            float r2 = __shfl_xor_sync(0xffffffffu, t2, 16);
            float r3 = __shfl_xor_sync(0xffffffffu, t3, 16);
            s[0] = (hi ? s[4] : s[0]) + r0;
            s[1] = (hi ? s[5] : s[1]) + r1;
            s[2] = (hi ? s[6] : s[2]) + r2;
            s[3] = (hi ? s[7] : s[3]) + r3;
            bool h3 = (lane & 8) != 0;
            t0 = h3 ? s[0] : s[2];
            t1 = h3 ? s[1] : s[3];
            r0 = __shfl_xor_sync(0xffffffffu, t0, 8);
            r1 = __shfl_xor_sync(0xffffffffu, t1, 8);
            s[0] = (h3 ? s[2] : s[0]) + r0;
            s[1] = (h3 ? s[3] : s[1]) + r1;
            bool h2 = (lane & 4) != 0;
            t0 = h2 ? s[0] : s[1];
            r0 = __shfl_xor_sync(0xffffffffu, t0, 4);
            s[0] = (h2 ? s[1] : s[0]) + r0;
            s[0] += __shfl_xor_sync(0xffffffffu, s[0], 2);
            s[0] += __shfl_xor_sync(0xffffffffu, s[0], 1);
        }
        if ((lane & 3) == 0) {
            int idx = ((lane >> 4) & 1) * 4 + ((lane >> 3) & 1) * 2 + ((lane >> 2) & 1);
            zsm[w][idx] = s[0];
        }
        __syncthreads();

        // ---- warp0: gates + state update + publish ----
        if (w == 0) {
            if (lane < 16) {
                float zi = zsm[uj][0 + q] + xzi;
                float zf = zsm[uj][2 + q] + xzf;
                float zg = zsm[uj][4 + q] + xzg;
                float zo = zsm[uj][6 + q] + xzo;
                float si = sigf(zi);
                float sf = sigf(zf);
                float tg = tanh_fast(zg);
                float so = sigf(zo);
                c = fmaf(sf, c, si * tg);
                float h = so * tanh_fast(c);
                hlast = h;
                hstage[q][uj] = h;
            }
            __syncwarp();
            if (lane == 0) {
                // lane 0 publishes all 16 h values itself, then one
                // red.release increment — the release orders the h stores.
                float4 a0 = *reinterpret_cast<float4*>(&hstage[0][0]);
                float4 a1 = *reinterpret_cast<float4*>(&hstage[0][4]);
                float4 b0 = *reinterpret_cast<float4*>(&hstage[1][0]);
                float4 b1 = *reinterpret_cast<float4*>(&hstage[1][4]);
                float* dA = hA_out + (size_t)(t + 1) * UDIM;
                float* dB = hB_out + (size_t)(t + 1) * UDIM;
                *reinterpret_cast<float4*>(dA)     = a0;
                *reinterpret_cast<float4*>(dA + 4) = a1;
                *reinterpret_cast<float4*>(dB)     = b0;
                *reinterpret_cast<float4*>(dB + 4) = b1;
                red_rel_add(cnt, 1u);
            }
        }
    }

    // final states -> out[2*T*U + p*1024 + u*2 + {0:h,1:c}]
    if (w == 0 && lane < 16) {
        float* os = out + (size_t)2 * T_STEPS * UDIM;
        os[myp * (UDIM * 2) + myunit * 2 + 0] = hlast;
        os[myp * (UDIM * 2) + myunit * 2 + 1] = c;
    }
}

// ---------------------------------------------------------------------------
// combine: real = h0 - h3, imag = h2 + h1
// ---------------------------------------------------------------------------
__global__ void combine_kernel(float* __restrict__ out)
{
    const int i = blockIdx.x * blockDim.x + threadIdx.x; // float4 index
    const int n4 = (T_STEPS * UDIM) / 4;
    if (i < n4) {
        const float4* H0 = reinterpret_cast<const float4*>(g_H + 0ULL * (T_STEPS + 1) * UDIM + UDIM);
        const float4* H1 = reinterpret_cast<const float4*>(g_H + 1ULL * (T_STEPS + 1) * UDIM + UDIM);
        const float4* H2 = reinterpret_cast<const float4*>(g_H + 2ULL * (T_STEPS + 1) * UDIM + UDIM);
        const float4* H3 = reinterpret_cast<const float4*>(g_H + 3ULL * (T_STEPS + 1) * UDIM + UDIM);
        float4 a = H0[i], b = H1[i], cc = H2[i], d = H3[i];
        float4 re, im;
        re.x = a.x - d.x; re.y = a.y - d.y; re.z = a.z - d.z; re.w = a.w - d.w;
        im.x = cc.x + b.x; im.y = cc.y + b.y; im.z = cc.z + b.z; im.w = cc.w + b.w;
        float4* o_re = reinterpret_cast<float4*>(out);
        float4* o_im = reinterpret_cast<float4*>(out + (size_t)T_STEPS * UDIM);
        o_re[i] = re;
        o_im[i] = im;
    }
}

// ---------------------------------------------------------------------------
extern "C" void kernel_launch(void* const* d_in, const int* in_sizes, int n_in,
                              void* d_out, int out_size)
{
    const float* in_real = (const float*)d_in[0];
    const float* in_imag = (const float*)d_in[1];
    const float* states  = (const float*)d_in[2];
    const float* Wr      = (const float*)d_in[3];
    const float* Rr      = (const float*)d_in[4];
    const float* br      = (const float*)d_in[5];
    const float* Wi      = (const float*)d_in[6];
    const float* Ri      = (const float*)d_in[7];
    const float* bi      = (const float*)d_in[8];
    float* out = (float*)d_out;

    init_kernel<<<2, 1024>>>(states);

    dim3 gg(GDIM / BN, (T_STEPS + BM - 1) / BM, 4); // (16, 63, 4)
    gemm_kernel<<<gg, 256>>>(in_real, in_imag, Wr, Wi, br, bi);

    rnn_kernel<<<128, 256>>>(Rr, Ri, states, out);

    combine_kernel<<<(T_STEPS * UDIM / 4 + 255) / 256, 256>>>(out);
}